// round 14
// baseline (speedup 1.0000x reference)
#include <cuda_runtime.h>
#include <cuda_bf16.h>
#include <math.h>
#include <cstdint>

// Problem constants
#define BATCH   2
#define SLEN    2048
#define DMODEL  1024
#define NHEADS  16
#define HEADDIM 64
#define NROWS   (BATCH * SLEN)      // 4096
#define NGROUPS (BATCH * NHEADS)    // 32 reshaped "heads"

// Scratch (allocation-free rule: __device__ globals)
__device__ float g_P[NROWS * DMODEL];
__device__ __nv_bfloat16 g_Qb[NROWS * DMODEL];
__device__ __nv_bfloat16 g_Kb[NROWS * DMODEL];
__device__ __nv_bfloat16 g_Vb[NROWS * DMODEL];
__device__ __nv_bfloat16 g_VTb[NROWS * DMODEL];  // per-group transposed V
__device__ __nv_bfloat16 g_Ob[NROWS * DMODEL];
__device__ __nv_bfloat16 g_Qin[NROWS * DMODEL];
__device__ __nv_bfloat16 g_Kin[NROWS * DMODEL];
__device__ __nv_bfloat16 g_Vin[NROWS * DMODEL];
__device__ __nv_bfloat16 g_WqT[DMODEL * DMODEL];
__device__ __nv_bfloat16 g_WkT[DMODEL * DMODEL];
__device__ __nv_bfloat16 g_WvT[DMODEL * DMODEL];
__device__ __nv_bfloat16 g_WoT[DMODEL * DMODEL];
__device__ unsigned long long g_Mb[BATCH * SLEN * (SLEN / 64)];  // packed mask bits

// ---------------------------------------------------------------------------
// Helpers (sm_80+ only — compute_103 rejects 'a'-gated PTX like tcgen05)
// ---------------------------------------------------------------------------
__device__ __forceinline__ uint32_t smem_u32(const void* p) {
    uint32_t a;
    asm("{ .reg .u64 t; cvta.to.shared.u64 t, %1; cvt.u32.u64 %0, t; }"
        : "=r"(a) : "l"(p));
    return a;
}

__device__ __forceinline__ void cp_async16(uint32_t saddr, const void* gaddr) {
    asm volatile("cp.async.cg.shared.global [%0], [%1], 16;"
                 :: "r"(saddr), "l"(gaddr) : "memory");
}
#define CP_COMMIT() asm volatile("cp.async.commit_group;" ::: "memory")
#define CP_WAIT1()  asm volatile("cp.async.wait_group 1;" ::: "memory")

__device__ __forceinline__ void mma_bf16(float* d, const uint32_t* a, const uint32_t* b) {
    asm volatile(
        "mma.sync.aligned.m16n8k16.row.col.f32.bf16.bf16.f32 "
        "{%0,%1,%2,%3}, {%4,%5,%6,%7}, {%8,%9}, {%0,%1,%2,%3};"
        : "+f"(d[0]), "+f"(d[1]), "+f"(d[2]), "+f"(d[3])
        : "r"(a[0]), "r"(a[1]), "r"(a[2]), "r"(a[3]), "r"(b[0]), "r"(b[1]));
}

__device__ __forceinline__ void ldsm_x4(uint32_t* r, uint32_t saddr) {
    asm volatile("ldmatrix.sync.aligned.m8n8.x4.shared.b16 {%0,%1,%2,%3}, [%4];"
                 : "=r"(r[0]), "=r"(r[1]), "=r"(r[2]), "=r"(r[3]) : "r"(saddr));
}

__device__ __forceinline__ uint32_t pack_bf16x2(float lo, float hi) {
    __nv_bfloat162 h = __floats2bfloat162_rn(lo, hi);
    return *reinterpret_cast<uint32_t*>(&h);
}

// ---------------------------------------------------------------------------
// Mask bit-pack (R13-validated): one uint64 per (row, 64-key word)
// ---------------------------------------------------------------------------
__global__ __launch_bounds__(256) void mask_pack(
    const unsigned char* __restrict__ m, unsigned long long* __restrict__ mb)
{
    const int idx = blockIdx.x * 256 + threadIdx.x;
    const uint4* p4 = reinterpret_cast<const uint4*>(m + (size_t)idx * 64);
    unsigned long long w = 0;
#pragma unroll
    for (int q = 0; q < 4; q++) {
        uint4 v = p4[q];
        uint32_t b = ((v.x * 0x01020408u) >> 24) & 0xFu;
        b |= (((v.y * 0x01020408u) >> 24) & 0xFu) << 4;
        b |= (((v.z * 0x01020408u) >> 24) & 0xFu) << 8;
        b |= (((v.w * 0x01020408u) >> 24) & 0xFu) << 12;
        w |= (unsigned long long)b << (q * 16);
    }
    mb[idx] = w;
}

// ---------------------------------------------------------------------------
// Fused fp32 -> bf16 conversion of q/k/v inputs
// ---------------------------------------------------------------------------
__global__ __launch_bounds__(256) void cvt_bf16_fused(
    const float* __restrict__ x0, const float* __restrict__ x1,
    const float* __restrict__ x2,
    __nv_bfloat16* __restrict__ y0, __nv_bfloat16* __restrict__ y1,
    __nv_bfloat16* __restrict__ y2)
{
    const int z = blockIdx.y;
    const float* x = (z == 0) ? x0 : (z == 1) ? x1 : x2;
    __nv_bfloat16* y = (z == 0) ? y0 : (z == 1) ? y1 : y2;
    const size_t i = ((size_t)blockIdx.x * 256 + threadIdx.x) * 8;
    float4 a = *(const float4*)(x + i);
    float4 b = *(const float4*)(x + i + 4);
    __nv_bfloat162* yp = reinterpret_cast<__nv_bfloat162*>(y + i);
    yp[0] = __floats2bfloat162_rn(a.x, a.y);
    yp[1] = __floats2bfloat162_rn(a.z, a.w);
    yp[2] = __floats2bfloat162_rn(b.x, b.y);
    yp[3] = __floats2bfloat162_rn(b.z, b.w);
}

// ---------------------------------------------------------------------------
// Fused weight transpose (fp32 -> bf16)
// ---------------------------------------------------------------------------
__global__ __launch_bounds__(256) void transpose1024_bf16_fused(
    const float* __restrict__ W0, const float* __restrict__ W1,
    const float* __restrict__ W2, const float* __restrict__ W3,
    __nv_bfloat16* __restrict__ T0, __nv_bfloat16* __restrict__ T1,
    __nv_bfloat16* __restrict__ T2, __nv_bfloat16* __restrict__ T3)
{
    const int z = blockIdx.z;
    const float* W = (z == 0) ? W0 : (z == 1) ? W1 : (z == 2) ? W2 : W3;
    __nv_bfloat16* Wt = (z == 0) ? T0 : (z == 1) ? T1 : (z == 2) ? T2 : T3;

    __shared__ float t[32][33];
    const int bx = blockIdx.x * 32, by = blockIdx.y * 32;
    const int x = threadIdx.x, y = threadIdx.y;
#pragma unroll
    for (int i = 0; i < 32; i += 8)
        t[y + i][x] = W[(size_t)(by + y + i) * DMODEL + bx + x];
    __syncthreads();
#pragma unroll
    for (int i = 0; i < 32; i += 8)
        Wt[(size_t)(bx + y + i) * DMODEL + by + x] = __float2bfloat16_rn(t[x][y + i]);
}

// ---------------------------------------------------------------------------
// V transpose per group (bf16): V[g][s][d] -> VT[g][d][s]
// ---------------------------------------------------------------------------
__global__ __launch_bounds__(256) void vtranspose_bf16(
    const __nv_bfloat16* __restrict__ V, __nv_bfloat16* __restrict__ VT)
{
    __shared__ __nv_bfloat16 t[32][34];
    const int g = blockIdx.z;
    const int s0 = blockIdx.x * 32, d0 = blockIdx.y * 32;
    const int x = threadIdx.x, y = threadIdx.y;
    const __nv_bfloat16* Vg = V + (size_t)g * SLEN * HEADDIM;
    __nv_bfloat16* VTg = VT + (size_t)g * SLEN * HEADDIM;
#pragma unroll
    for (int i = 0; i < 32; i += 8)
        t[y + i][x] = Vg[(size_t)(s0 + y + i) * HEADDIM + d0 + x];
    __syncthreads();
#pragma unroll
    for (int i = 0; i < 32; i += 8)
        VTg[(size_t)(d0 + y + i) * SLEN + s0 + x] = t[x][y + i];
}

// ---------------------------------------------------------------------------
// HMMA bf16 GEMM: CTA 128x128, BK=64, 8 warps (4x2), warp 32x64.
// R14: 3-stage cp.async pipeline, ONE __syncthreads per chunk. Registers
// (126/thread) limit occupancy to 2 CTAs/SM, so the 110.6 KB smem is free
// (2 x 110.6 <= 227 KB). R9/R10 bisect showed this ordering is ~12us faster.
// ---------------------------------------------------------------------------
#define KSW 36
#define TILE_WORDS (128 * KSW)
#define GEMM_SMEM (6 * TILE_WORDS * 4)   // 110592 B

__global__ __launch_bounds__(256) void gemm_bf16_qkv(
    const __nv_bfloat16* __restrict__ A0, const __nv_bfloat16* __restrict__ A1,
    const __nv_bfloat16* __restrict__ A2,
    const __nv_bfloat16* __restrict__ B0, const __nv_bfloat16* __restrict__ B1,
    const __nv_bfloat16* __restrict__ B2,
    __nv_bfloat16* __restrict__ C0, __nv_bfloat16* __restrict__ C1,
    __nv_bfloat16* __restrict__ C2, int M, int N, int K)
{
    extern __shared__ uint32_t shw[];

    const int z = blockIdx.z;
    const __nv_bfloat16* A = (z == 0) ? A0 : (z == 1) ? A1 : A2;
    const __nv_bfloat16* Bt = (z == 0) ? B0 : (z == 1) ? B1 : B2;
    __nv_bfloat16* C = (z == 0) ? C0 : (z == 1) ? C1 : C2;

    const int tid = threadIdx.x;
    const int wid = tid >> 5;
    const int lane = tid & 31;
    const int mb = (wid & 3) * 32;
    const int nb = (wid >> 2) * 64;
    const int g = lane >> 2;
    const int t = lane & 3;
    const int m0 = blockIdx.y * 128;
    const int n0 = blockIdx.x * 128;

    const int quad = lane >> 3;
    const int within = lane & 7;
    const int arow = (quad & 1) * 8 + within;
    const int acol = (quad >> 1) * 4;
    const int brow = (quad >> 1) * 8 + within;
    const int bcol = (quad & 1) * 4;

    const uint32_t aoff0 = (uint32_t)((mb + arow) * KSW + acol) * 4u;
    const uint32_t aoff1 = (uint32_t)((mb + 16 + arow) * KSW + acol) * 4u;
    uint32_t boff[4];
#pragma unroll
    for (int ntp = 0; ntp < 4; ntp++)
        boff[ntp] = (uint32_t)((nb + ntp * 16 + brow) * KSW + bcol) * 4u;

    uint32_t saw[3], sbw[3];
#pragma unroll
    for (int s = 0; s < 3; s++) {
        saw[s] = smem_u32(shw + s * TILE_WORDS);
        sbw[s] = smem_u32(shw + (3 + s) * TILE_WORDS);
    }

    float acc[2][8][4];
#pragma unroll
    for (int i = 0; i < 2; i++)
#pragma unroll
        for (int j = 0; j < 8; j++)
#pragma unroll
            for (int q = 0; q < 4; q++) acc[i][j][q] = 0.f;

    const int NCH = K / 64;

    auto issue = [&](int c, int b) {
        const __nv_bfloat16* Ag = A + (size_t)m0 * K + (size_t)c * 64;
        const __nv_bfloat16* Bg = Bt + (size_t)n0 * K + (size_t)c * 64;
#pragma unroll
        for (int i = 0; i < 4; i++) {
            const int u = tid + 256 * i;
            const int row = u >> 3;
            const int seg = u & 7;
            const uint32_t so = (uint32_t)(row * KSW + seg * 4) * 4u;
            cp_async16(saw[b] + so, Ag + (size_t)row * K + seg * 8);
            cp_async16(sbw[b] + so, Bg + (size_t)row * K + seg * 8);
        }
        CP_COMMIT();
    };

    issue(0, 0);
    issue(1, 1);

    for (int c = 0; c < NCH; c++) {
        const int b = c % 3;
        CP_WAIT1();
        __syncthreads();            // chunk c visible; buffer (c+2)%3 retired
        if (c + 2 < NCH) issue(c + 2, (c + 2) % 3);
        else CP_COMMIT();
#pragma unroll
        for (int s = 0; s < 4; s++) {
            const uint32_t ks = (uint32_t)s * 32u;
            uint32_t af0[4], af1[4];
            ldsm_x4(af0, saw[b] + aoff0 + ks);
            ldsm_x4(af1, saw[b] + aoff1 + ks);
#pragma unroll
            for (int ntp = 0; ntp < 4; ntp++) {
                uint32_t bq[4];
                ldsm_x4(bq, sbw[b] + boff[ntp] + ks);
                mma_bf16(acc[0][2 * ntp],     af0, bq);
                mma_bf16(acc[1][2 * ntp],     af1, bq);
                mma_bf16(acc[0][2 * ntp + 1], af0, bq + 2);
                mma_bf16(acc[1][2 * ntp + 1], af1, bq + 2);
            }
        }
    }

#pragma unroll
    for (int mt = 0; mt < 2; mt++) {
        const int r = m0 + mb + mt * 16 + g;
#pragma unroll
        for (int nt = 0; nt < 8; nt++) {
            const int cx = n0 + nb + nt * 8 + 2 * t;
            uint32_t w0 = pack_bf16x2(acc[mt][nt][0], acc[mt][nt][1]);
            uint32_t w1 = pack_bf16x2(acc[mt][nt][2], acc[mt][nt][3]);
            *reinterpret_cast<uint32_t*>(C + (size_t)r * N + cx) = w0;
            *reinterpret_cast<uint32_t*>(C + (size_t)(r + 8) * N + cx) = w1;
        }
    }
}

__global__ __launch_bounds__(256) void gemm_bf16_out(
    const __nv_bfloat16* __restrict__ A, const __nv_bfloat16* __restrict__ Bt,
    const float* __restrict__ bias, float* __restrict__ C,
    int M, int N, int K)
{
    extern __shared__ uint32_t shw[];

    const int tid = threadIdx.x;
    const int wid = tid >> 5;
    const int lane = tid & 31;
    const int mb = (wid & 3) * 32;
    const int nb = (wid >> 2) * 64;
    const int g = lane >> 2;
    const int t = lane & 3;
    const int m0 = blockIdx.y * 128;
    const int n0 = blockIdx.x * 128;

    const int quad = lane >> 3;
    const int within = lane & 7;
    const int arow = (quad & 1) * 8 + within;
    const int acol = (quad >> 1) * 4;
    const int brow = (quad >> 1) * 8 + within;
    const int bcol = (quad & 1) * 4;

    const uint32_t aoff0 = (uint32_t)((mb + arow) * KSW + acol) * 4u;
    const uint32_t aoff1 = (uint32_t)((mb + 16 + arow) * KSW + acol) * 4u;
    uint32_t boff[4];
#pragma unroll
    for (int ntp = 0; ntp < 4; ntp++)
        boff[ntp] = (uint32_t)((nb + ntp * 16 + brow) * KSW + bcol) * 4u;

    uint32_t saw[3], sbw[3];
#pragma unroll
    for (int s = 0; s < 3; s++) {
        saw[s] = smem_u32(shw + s * TILE_WORDS);
        sbw[s] = smem_u32(shw + (3 + s) * TILE_WORDS);
    }

    float acc[2][8][4];
#pragma unroll
    for (int i = 0; i < 2; i++)
#pragma unroll
        for (int j = 0; j < 8; j++)
#pragma unroll
            for (int q = 0; q < 4; q++) acc[i][j][q] = 0.f;

    const int NCH = K / 64;

    auto issue = [&](int c, int b) {
        const __nv_bfloat16* Ag = A + (size_t)m0 * K + (size_t)c * 64;
        const __nv_bfloat16* Bg = Bt + (size_t)n0 * K + (size_t)c * 64;
#pragma unroll
        for (int i = 0; i < 4; i++) {
            const int u = tid + 256 * i;
            const int row = u >> 3;
            const int seg = u & 7;
            const uint32_t so = (uint32_t)(row * KSW + seg * 4) * 4u;
            cp_async16(saw[b] + so, Ag + (size_t)row * K + seg * 8);
            cp_async16(sbw[b] + so, Bg + (size_t)row * K + seg * 8);
        }
        CP_COMMIT();
    };

    issue(0, 0);
    issue(1, 1);

    for (int c = 0; c < NCH; c++) {
        const int b = c % 3;
        CP_WAIT1();
        __syncthreads();
        if (c + 2 < NCH) issue(c + 2, (c + 2) % 3);
        else CP_COMMIT();
#pragma unroll
        for (int s = 0; s < 4; s++) {
            const uint32_t ks = (uint32_t)s * 32u;
            uint32_t af0[4], af1[4];
            ldsm_x4(af0, saw[b] + aoff0 + ks);
            ldsm_x4(af1, saw[b] + aoff1 + ks);
#pragma unroll
            for (int ntp = 0; ntp < 4; ntp++) {
                uint32_t bq[4];
                ldsm_x4(bq, sbw[b] + boff[ntp] + ks);
                mma_bf16(acc[0][2 * ntp],     af0, bq);
                mma_bf16(acc[1][2 * ntp],     af1, bq);
                mma_bf16(acc[0][2 * ntp + 1], af0, bq + 2);
                mma_bf16(acc[1][2 * ntp + 1], af1, bq + 2);
            }
        }
    }

#pragma unroll
    for (int mt = 0; mt < 2; mt++) {
        const int r = m0 + mb + mt * 16 + g;
#pragma unroll
        for (int nt = 0; nt < 8; nt++) {
            const int cx = n0 + nb + nt * 8 + 2 * t;
            const float b0 = __ldg(&bias[cx]);
            const float b1 = __ldg(&bias[cx + 1]);
            float2 v0, v1;
            v0.x = acc[mt][nt][0] + b0; v0.y = acc[mt][nt][1] + b1;
            v1.x = acc[mt][nt][2] + b0; v1.y = acc[mt][nt][3] + b1;
            *(float2*)(C + (size_t)r * N + cx) = v0;
            *(float2*)(C + (size_t)(r + 8) * N + cx) = v1;
        }
    }
}

// ---------------------------------------------------------------------------
// bf16 HMMA flash attention. Q,K bf16 [32][2048][64]; VT bf16 [32][64][2048].
// CTA: 128 Q rows x 1 group, 8 warps. P in registers (R12), packed-bit mask
// (R13). R14: 3-stage K/V cp.async pipeline, ONE __syncthreads per tile.
// Smem 55296 B (6 tiles); Q staged through first 18432 B pre-loop.
// ---------------------------------------------------------------------------
#define AKW 36
#define ATT_TILE (64 * AKW)
#define ATT_SMEM (6 * ATT_TILE * 4)   // 55296 B

__global__ __launch_bounds__(256) void attn_bf16(
    const __nv_bfloat16* __restrict__ Q, const __nv_bfloat16* __restrict__ K,
    const __nv_bfloat16* __restrict__ VT,
    const unsigned long long* __restrict__ maskbits,
    __nv_bfloat16* __restrict__ O)
{
    extern __shared__ uint32_t smw[];

    const int tid = threadIdx.x;
    const int wid = tid >> 5;
    const int lane = tid & 31;
    const int gq = lane >> 2;
    const int t = lane & 3;
    const int qb = blockIdx.x;
    const int grp = blockIdx.y;
    const int r0 = wid * 16;

    const int quad = lane >> 3;
    const int within = lane & 7;
    const int arow = (quad & 1) * 8 + within;
    const int acol = (quad >> 1) * 4;
    const int brow = (quad >> 1) * 8 + within;
    const int bcol = (quad & 1) * 4;

    uint32_t boffA[4];
#pragma unroll
    for (int ntp = 0; ntp < 4; ntp++)
        boffA[ntp] = (uint32_t)((ntp * 16 + brow) * AKW + bcol) * 4u;

    uint32_t skw[3], svw[3];
#pragma unroll
    for (int s = 0; s < 3; s++) {
        skw[s] = smem_u32(smw + s * ATT_TILE);
        svw[s] = smem_u32(smw + (3 + s) * ATT_TILE);
    }

    const __nv_bfloat16* Qg = Q + ((size_t)grp * SLEN + qb * 128 + r0) * HEADDIM;
    const __nv_bfloat16* Kg = K + (size_t)grp * SLEN * HEADDIM;
    const __nv_bfloat16* VTg = VT + (size_t)grp * SLEN * HEADDIM;
    const unsigned long long* mw =
        maskbits + ((size_t)(grp % BATCH) * SLEN + (size_t)(qb * 128 + r0)) * (SLEN / 64);

    auto issue = [&](int kt, int b) {
#pragma unroll
        for (int i = 0; i < 2; i++) {
            const int u = tid + 256 * i;
            const int row = u >> 3;
            const int seg = u & 7;
            const uint32_t so = (uint32_t)(row * AKW + seg * 4) * 4u;
            cp_async16(skw[b] + so, Kg + (size_t)(kt * 64 + row) * HEADDIM + seg * 8);
            cp_async16(svw[b] + so, VTg + (size_t)row * SLEN + kt * 64 + seg * 8);
        }
        CP_COMMIT();
    };

    // ---- Stage Q through the tile-buffer region, build persistent A frags
    uint32_t* sQw = smw + r0 * AKW;
    const uint32_t sq_addr = smem_u32(sQw) + (uint32_t)(arow * AKW + acol) * 4u;
    {
        const int row = lane >> 1;
        const int cs = (lane & 1) * 16;
#pragma unroll
        for (int j = 0; j < 4; j++) {
            uint4 v = *(const uint4*)(Qg + (size_t)row * HEADDIM + (cs + j * 4) * 2);
            *(uint4*)&sQw[row * AKW + cs + j * 4] = v;
        }
    }
    __syncwarp();
    uint32_t qf[4][4];
#pragma unroll
    for (int s = 0; s < 4; s++)
        ldsm_x4(qf[s], sq_addr + (uint32_t)s * 32u);
    __syncthreads();   // Q fragments captured before buffers reused by cp.async

    issue(0, 0);
    issue(1, 1);

    float oacc[8][4];
#pragma unroll
    for (int nt = 0; nt < 8; nt++)
#pragma unroll
        for (int q = 0; q < 4; q++) oacc[nt][q] = 0.f;
    float mA = -INFINITY, mB = -INFINITY, lA = 0.f, lB = 0.f;

    const float scale = 0.125f;
    const int NT = SLEN / 64;

    for (int kt = 0; kt < NT; kt++) {
        const int b = kt % 3;
        CP_WAIT1();
        __syncthreads();          // tile kt visible; buffer (kt+2)%3 retired
        if (kt + 2 < NT) issue(kt + 2, (kt + 2) % 3);
        else CP_COMMIT();

        // ---- S = Q K^T
        float sacc[8][4];
#pragma unroll
        for (int nt = 0; nt < 8; nt++)
#pragma unroll
            for (int q = 0; q < 4; q++) sacc[nt][q] = 0.f;
#pragma unroll
        for (int s = 0; s < 4; s++) {
            const uint32_t ks = (uint32_t)s * 32u;
#pragma unroll
            for (int ntp = 0; ntp < 4; ntp++) {
                uint32_t bq[4];
                ldsm_x4(bq, skw[b] + boffA[ntp] + ks);
                mma_bf16(sacc[2 * ntp],     qf[s], bq);
                mma_bf16(sacc[2 * ntp + 1], qf[s], bq + 2);
            }
        }

        // ---- Mask + scale (packed bits, warp-uniform fast path)
        const unsigned long long wA = mw[(size_t)gq * (SLEN / 64) + kt];
        const unsigned long long wB = mw[(size_t)(gq + 8) * (SLEN / 64) + kt];
        if (__all_sync(0xffffffffu, (wA | wB) == 0ull)) {
#pragma unroll
            for (int nt = 0; nt < 8; nt++) {
                sacc[nt][0] *= scale; sacc[nt][1] *= scale;
                sacc[nt][2] *= scale; sacc[nt][3] *= scale;
            }
        } else {
#pragma unroll
            for (int nt = 0; nt < 8; nt++) {
                const int c0 = nt * 8 + 2 * t;
                sacc[nt][0] = ((wA >> c0) & 1ull) ? -1e9f : sacc[nt][0] * scale;
                sacc[nt][1] = ((wA >> (c0 + 1)) & 1ull) ? -1e9f : sacc[nt][1] * scale;
                sacc[nt][2] = ((wB >> c0) & 1ull) ? -1e9f : sacc[nt][2] * scale;
                sacc[nt][3] = ((wB >> (c0 + 1)) & 1ull) ? -1e9f : sacc[nt][3] * scale;
            }
        }

        // ---- Online softmax
        float mxA = -INFINITY, mxB = -INFINITY;
#pragma unroll
        for (int nt = 0; nt < 8; nt++) {
            mxA = fmaxf(mxA, fmaxf(sacc[nt][0], sacc[nt][1]));
            mxB = fmaxf(mxB, fmaxf(sacc[nt][2], sacc[nt][3]));
        }
        mxA = fmaxf(mxA, __shfl_xor_sync(0xffffffffu, mxA, 1));
        mxA = fmaxf(mxA, __shfl_xor_sync(0xffffffffu, mxA, 2));
        mxB = fmaxf(mxB, __shfl_xor_sync(0xffffffffu, mxB, 1));
        mxB = fmaxf(mxB, __shfl_xor_sync(0xffffffffu, mxB, 2));

        const float mnA = fmaxf(mA, mxA);
        const float mnB = fmaxf(mB, mxB);
        const float cA = __expf(mA - mnA);
        const float cB = __expf(mB - mnB);
        float suA = 0.f, suB = 0.f;
#pragma unroll
        for (int nt = 0; nt < 8; nt++) {
            sacc[nt][0] = __expf(sacc[nt][0] - mnA);
            sacc[nt][1] = __expf(sacc[nt][1] - mnA);
            sacc[nt][2] = __expf(sacc[nt][2] - mnB);
            sacc[nt][3] = __expf(sacc[nt][3] - mnB);
            suA += sacc[nt][0] + sacc[nt][1];
            suB += sacc[nt][2] + sacc[nt][3];
        }
        suA += __shfl_xor_sync(0xffffffffu, suA, 1);
        suA += __shfl_xor_sync(0xffffffffu, suA, 2);
        suB += __shfl_xor_sync(0xffffffffu, suB, 1);
        suB += __shfl_xor_sync(0xffffffffu, suB, 2);
        lA = lA * cA + suA;
        lB = lB * cB + suB;
        mA = mnA;
        mB = mnB;
#pragma unroll
        for (int nt = 0; nt < 8; nt++) {
            oacc[nt][0] *= cA; oacc[nt][1] *= cA;
            oacc[nt][2] *= cB; oacc[nt][3] *= cB;
        }

        // ---- P A-fragments direct from registers (R12-validated mapping)
        uint32_t pf[4][4];
#pragma unroll
        for (int s = 0; s < 4; s++) {
            pf[s][0] = pack_bf16x2(sacc[2 * s][0],     sacc[2 * s][1]);
            pf[s][1] = pack_bf16x2(sacc[2 * s][2],     sacc[2 * s][3]);
            pf[s][2] = pack_bf16x2(sacc[2 * s + 1][0], sacc[2 * s + 1][1]);
            pf[s][3] = pack_bf16x2(sacc[2 * s + 1][2], sacc[2 * s + 1][3]);
        }

        // ---- O += P V  (A=P from registers; B=VT ldmatrix)
#pragma unroll
        for (int s = 0; s < 4; s++) {
            const uint32_t ks = (uint32_t)s * 32u;
#pragma unroll
            for (int ntp = 0; ntp < 4; ntp++) {
                uint32_t bq[4];
                ldsm_x4(bq, svw[b] + boffA[ntp] + ks);
                mma_bf16(oacc[2 * ntp],     pf[s], bq);
                mma_bf16(oacc[2 * ntp + 1], pf[s], bq + 2);
            }
        }
    }

    // ---- Normalize + write O as bf16
    const float iA = 1.f / lA;
    const float iB = 1.f / lB;
    __nv_bfloat16* Og = O + ((size_t)grp * SLEN + qb * 128 + r0) * HEADDIM;
#pragma unroll
    for (int nt = 0; nt < 8; nt++) {
        const int cb = nt * 8 + 2 * t;
        uint32_t wA = pack_bf16x2(oacc[nt][0] * iA, oacc[nt][1] * iA);
        uint32_t wB = pack_bf16x2(oacc[nt][2] * iB, oacc[nt][3] * iB);
        *reinterpret_cast<uint32_t*>(Og + (size_t)gq * HEADDIM + cb) = wA;
        *reinterpret_cast<uint32_t*>(Og + (size_t)(gq + 8) * HEADDIM + cb) = wB;
    }
}

// ---------------------------------------------------------------------------
// Fused residual + LayerNorm (unchanged)
// ---------------------------------------------------------------------------
__global__ __launch_bounds__(256) void ln_kernel(
    const float* __restrict__ x, const float* __restrict__ p,
    const float* __restrict__ gamma, const float* __restrict__ beta,
    float* __restrict__ out)
{
    const int row = blockIdx.x;
    const int t = threadIdx.x;
    const size_t base = (size_t)row * DMODEL + t * 4;

    float4 xv = *(const float4*)(x + base);
    float4 pv = *(const float4*)(p + base);
    float v0 = xv.x + pv.x, v1 = xv.y + pv.y, v2 = xv.z + pv.z, v3 = xv.w + pv.w;

    __shared__ float red[8];
    float s = v0 + v1 + v2 + v3;
#pragma unroll
    for (int off = 16; off >= 1; off >>= 1) s += __shfl_xor_sync(0xffffffffu, s, off);
    if ((t & 31) == 0) red[t >> 5] = s;
    __syncthreads();
    float mu = (red[0] + red[1] + red[2] + red[3] +
                red[4] + red[5] + red[6] + red[7]) * (1.f / DMODEL);
    __syncthreads();

    float d0 = v0 - mu, d1 = v1 - mu, d2 = v2 - mu, d3 = v3 - mu;
    float q = d0 * d0 + d1 * d1 + d2 * d2 + d3 * d3;
#pragma unroll
    for (int off = 16; off >= 1; off >>= 1) q += __shfl_xor_sync(0xffffffffu, q, off);
    if ((t & 31) == 0) red[t >> 5] = q;
    __syncthreads();
    float var = (red[0] + red[1] + red[2] + red[3] +
                 red[4] + red[5] + red[6] + red[7]) * (1.f / DMODEL);
    float rs = rsqrtf(var + 1e-5f);

    float4 gv = *(const float4*)(gamma + t * 4);
    float4 bv = *(const float4*)(beta + t * 4);
    float4 ov;
    ov.x = d0 * rs * gv.x + bv.x;
    ov.y = d1 * rs * gv.y + bv.y;
    ov.z = d2 * rs * gv.z + bv.z;
    ov.w = d3 * rs * gv.w + bv.w;
    *(float4*)(out + base) = ov;
}

// ---------------------------------------------------------------------------
// Launch
// ---------------------------------------------------------------------------
extern "C" void kernel_launch(void* const* d_in, const int* in_sizes, int n_in,
                              void* d_out, int out_size)
{
    (void)in_sizes; (void)n_in; (void)out_size;
    const float* q_in  = (const float*)d_in[0];
    const float* k_in  = (const float*)d_in[1];
    const float* v_in  = (const float*)d_in[2];
    const unsigned char* mask = (const unsigned char*)d_in[3];
    const float* Wq = (const float*)d_in[4];
    const float* Wk = (const float*)d_in[5];
    const float* Wv = (const float*)d_in[6];
    const float* Wo = (const float*)d_in[7];
    const float* bo = (const float*)d_in[8];
    const float* gamma = (const float*)d_in[9];
    const float* beta  = (const float*)d_in[10];
    float* out = (float*)d_out;

    float* pP;
    __nv_bfloat16 *pQb, *pKb, *pVb, *pVTb, *pOb, *pQin, *pKin, *pVin;
    __nv_bfloat16 *pWqT, *pWkT, *pWvT, *pWoT;
    unsigned long long* pMb;
    cudaGetSymbolAddress((void**)&pP, g_P);
    cudaGetSymbolAddress((void**)&pQb, g_Qb);
    cudaGetSymbolAddress((void**)&pKb, g_Kb);
    cudaGetSymbolAddress((void**)&pVb, g_Vb);
    cudaGetSymbolAddress((void**)&pVTb, g_VTb);
    cudaGetSymbolAddress((void**)&pOb, g_Ob);
    cudaGetSymbolAddress((void**)&pQin, g_Qin);
    cudaGetSymbolAddress((void**)&pKin, g_Kin);
    cudaGetSymbolAddress((void**)&pVin, g_Vin);
    cudaGetSymbolAddress((void**)&pWqT, g_WqT);
    cudaGetSymbolAddress((void**)&pWkT, g_WkT);
    cudaGetSymbolAddress((void**)&pWvT, g_WvT);
    cudaGetSymbolAddress((void**)&pWoT, g_WoT);
    cudaGetSymbolAddress((void**)&pMb, g_Mb);

    cudaFuncSetAttribute(gemm_bf16_qkv, cudaFuncAttributeMaxDynamicSharedMemorySize, GEMM_SMEM);
    cudaFuncSetAttribute(gemm_bf16_out, cudaFuncAttributeMaxDynamicSharedMemorySize, GEMM_SMEM);
    cudaFuncSetAttribute(attn_bf16, cudaFuncAttributeMaxDynamicSharedMemorySize, ATT_SMEM);

    // launch 0: fused weight transposes
    dim3 tgrid(DMODEL / 32, DMODEL / 32, 4);
    dim3 tblk(32, 8);
    transpose1024_bf16_fused<<<tgrid, tblk>>>(Wq, Wk, Wv, Wo, pWqT, pWkT, pWvT, pWoT);

    // launch 1: fused input conversion
    dim3 cgrid(NROWS * DMODEL / (256 * 8), 3);
    cvt_bf16_fused<<<cgrid, 256>>>(q_in, k_in, v_in, pQin, pKin, pVin);

    // launch 2: mask bit-pack
    mask_pack<<<BATCH * SLEN * (SLEN / 64) / 256, 256>>>(mask, pMb);

    // launch 3: batched Q/K/V projections
    dim3 ggrid3(DMODEL / 128, NROWS / 128, 3);
    gemm_bf16_qkv<<<ggrid3, 256, GEMM_SMEM>>>(
        pQin, pKin, pVin, pWqT, pWkT, pWvT, pQb, pKb, pVb,
        NROWS, DMODEL, DMODEL);

    // launch 4: V -> VT per group
    dim3 vgrid(SLEN / 32, HEADDIM / 32, NGROUPS);
    vtranspose_bf16<<<vgrid, tblk>>>(pVb, pVTb);

    // launch 5: attention
    dim3 agrid(SLEN / 128, NGROUPS);
    attn_bf16<<<agrid, 256, ATT_SMEM>>>(pQb, pKb, pVTb, pMb, pOb);

    // launch 6: output projection (+bias, fp32 out)
    dim3 ggrid1(DMODEL / 128, NROWS / 128);
    gemm_bf16_out<<<ggrid1, 256, GEMM_SMEM>>>(pOb, pWoT, bo, pP, NROWS, DMODEL, DMODEL);

    // launch 7: residual + LayerNorm
    ln_kernel<<<NROWS, 256>>>(q_in, pP, gamma, beta, out);
}

// round 15
// speedup vs baseline: 1.2109x; 1.2109x over previous
#include <cuda_runtime.h>
#include <cuda_bf16.h>
#include <math.h>
#include <cstdint>

// Problem constants
#define BATCH   2
#define SLEN    2048
#define DMODEL  1024
#define NHEADS  16
#define HEADDIM 64
#define NROWS   (BATCH * SLEN)      // 4096
#define NGROUPS (BATCH * NHEADS)    // 32 reshaped "heads"

// Scratch (allocation-free rule: __device__ globals)
__device__ float g_P[NROWS * DMODEL];
__device__ __nv_bfloat16 g_Qb[NROWS * DMODEL];
__device__ __nv_bfloat16 g_Kb[NROWS * DMODEL];
__device__ __nv_bfloat16 g_Vb[NROWS * DMODEL];
__device__ __nv_bfloat16 g_VTb[NROWS * DMODEL];  // per-group transposed V
__device__ __nv_bfloat16 g_Ob[NROWS * DMODEL];
__device__ __nv_bfloat16 g_Qin[NROWS * DMODEL];
__device__ __nv_bfloat16 g_Kin[NROWS * DMODEL];
__device__ __nv_bfloat16 g_Vin[NROWS * DMODEL];
__device__ __nv_bfloat16 g_WqT[DMODEL * DMODEL];
__device__ __nv_bfloat16 g_WkT[DMODEL * DMODEL];
__device__ __nv_bfloat16 g_WvT[DMODEL * DMODEL];
__device__ __nv_bfloat16 g_WoT[DMODEL * DMODEL];
__device__ unsigned long long g_Mb[BATCH * SLEN * (SLEN / 64)];  // packed mask bits

// ---------------------------------------------------------------------------
// Helpers (sm_80+ only — compute_103 rejects 'a'-gated PTX like tcgen05)
// ---------------------------------------------------------------------------
__device__ __forceinline__ uint32_t smem_u32(const void* p) {
    uint32_t a;
    asm("{ .reg .u64 t; cvta.to.shared.u64 t, %1; cvt.u32.u64 %0, t; }"
        : "=r"(a) : "l"(p));
    return a;
}

__device__ __forceinline__ void cp_async16(uint32_t saddr, const void* gaddr) {
    asm volatile("cp.async.cg.shared.global [%0], [%1], 16;"
                 :: "r"(saddr), "l"(gaddr) : "memory");
}
#define CP_COMMIT() asm volatile("cp.async.commit_group;" ::: "memory")
#define CP_WAIT1()  asm volatile("cp.async.wait_group 1;" ::: "memory")

__device__ __forceinline__ void mma_bf16(float* d, const uint32_t* a, const uint32_t* b) {
    asm volatile(
        "mma.sync.aligned.m16n8k16.row.col.f32.bf16.bf16.f32 "
        "{%0,%1,%2,%3}, {%4,%5,%6,%7}, {%8,%9}, {%0,%1,%2,%3};"
        : "+f"(d[0]), "+f"(d[1]), "+f"(d[2]), "+f"(d[3])
        : "r"(a[0]), "r"(a[1]), "r"(a[2]), "r"(a[3]), "r"(b[0]), "r"(b[1]));
}

__device__ __forceinline__ void ldsm_x4(uint32_t* r, uint32_t saddr) {
    asm volatile("ldmatrix.sync.aligned.m8n8.x4.shared.b16 {%0,%1,%2,%3}, [%4];"
                 : "=r"(r[0]), "=r"(r[1]), "=r"(r[2]), "=r"(r[3]) : "r"(saddr));
}

__device__ __forceinline__ uint32_t pack_bf16x2(float lo, float hi) {
    __nv_bfloat162 h = __floats2bfloat162_rn(lo, hi);
    return *reinterpret_cast<uint32_t*>(&h);
}

// ---------------------------------------------------------------------------
// Mask bit-pack (R13-validated)
// ---------------------------------------------------------------------------
__global__ __launch_bounds__(256) void mask_pack(
    const unsigned char* __restrict__ m, unsigned long long* __restrict__ mb)
{
    const int idx = blockIdx.x * 256 + threadIdx.x;
    const uint4* p4 = reinterpret_cast<const uint4*>(m + (size_t)idx * 64);
    unsigned long long w = 0;
#pragma unroll
    for (int q = 0; q < 4; q++) {
        uint4 v = p4[q];
        uint32_t b = ((v.x * 0x01020408u) >> 24) & 0xFu;
        b |= (((v.y * 0x01020408u) >> 24) & 0xFu) << 4;
        b |= (((v.z * 0x01020408u) >> 24) & 0xFu) << 8;
        b |= (((v.w * 0x01020408u) >> 24) & 0xFu) << 12;
        w |= (unsigned long long)b << (q * 16);
    }
    mb[idx] = w;
}

// ---------------------------------------------------------------------------
// Fused fp32 -> bf16 conversion of q/k/v inputs
// ---------------------------------------------------------------------------
__global__ __launch_bounds__(256) void cvt_bf16_fused(
    const float* __restrict__ x0, const float* __restrict__ x1,
    const float* __restrict__ x2,
    __nv_bfloat16* __restrict__ y0, __nv_bfloat16* __restrict__ y1,
    __nv_bfloat16* __restrict__ y2)
{
    const int z = blockIdx.y;
    const float* x = (z == 0) ? x0 : (z == 1) ? x1 : x2;
    __nv_bfloat16* y = (z == 0) ? y0 : (z == 1) ? y1 : y2;
    const size_t i = ((size_t)blockIdx.x * 256 + threadIdx.x) * 8;
    float4 a = *(const float4*)(x + i);
    float4 b = *(const float4*)(x + i + 4);
    __nv_bfloat162* yp = reinterpret_cast<__nv_bfloat162*>(y + i);
    yp[0] = __floats2bfloat162_rn(a.x, a.y);
    yp[1] = __floats2bfloat162_rn(a.z, a.w);
    yp[2] = __floats2bfloat162_rn(b.x, b.y);
    yp[3] = __floats2bfloat162_rn(b.z, b.w);
}

// ---------------------------------------------------------------------------
// Fused weight transpose (fp32 -> bf16)
// ---------------------------------------------------------------------------
__global__ __launch_bounds__(256) void transpose1024_bf16_fused(
    const float* __restrict__ W0, const float* __restrict__ W1,
    const float* __restrict__ W2, const float* __restrict__ W3,
    __nv_bfloat16* __restrict__ T0, __nv_bfloat16* __restrict__ T1,
    __nv_bfloat16* __restrict__ T2, __nv_bfloat16* __restrict__ T3)
{
    const int z = blockIdx.z;
    const float* W = (z == 0) ? W0 : (z == 1) ? W1 : (z == 2) ? W2 : W3;
    __nv_bfloat16* Wt = (z == 0) ? T0 : (z == 1) ? T1 : (z == 2) ? T2 : T3;

    __shared__ float t[32][33];
    const int bx = blockIdx.x * 32, by = blockIdx.y * 32;
    const int x = threadIdx.x, y = threadIdx.y;
#pragma unroll
    for (int i = 0; i < 32; i += 8)
        t[y + i][x] = W[(size_t)(by + y + i) * DMODEL + bx + x];
    __syncthreads();
#pragma unroll
    for (int i = 0; i < 32; i += 8)
        Wt[(size_t)(bx + y + i) * DMODEL + by + x] = __float2bfloat16_rn(t[x][y + i]);
}

// ---------------------------------------------------------------------------
// V transpose per group (bf16): V[g][s][d] -> VT[g][d][s]
// ---------------------------------------------------------------------------
__global__ __launch_bounds__(256) void vtranspose_bf16(
    const __nv_bfloat16* __restrict__ V, __nv_bfloat16* __restrict__ VT)
{
    __shared__ __nv_bfloat16 t[32][34];
    const int g = blockIdx.z;
    const int s0 = blockIdx.x * 32, d0 = blockIdx.y * 32;
    const int x = threadIdx.x, y = threadIdx.y;
    const __nv_bfloat16* Vg = V + (size_t)g * SLEN * HEADDIM;
    __nv_bfloat16* VTg = VT + (size_t)g * SLEN * HEADDIM;
#pragma unroll
    for (int i = 0; i < 32; i += 8)
        t[y + i][x] = Vg[(size_t)(s0 + y + i) * HEADDIM + d0 + x];
    __syncthreads();
#pragma unroll
    for (int i = 0; i < 32; i += 8)
        VTg[(size_t)(d0 + y + i) * SLEN + s0 + x] = t[x][y + i];
}

// ---------------------------------------------------------------------------
// HMMA bf16 GEMM: CTA 128x128, BK=64, 8 warps (4x2), warp 32x64.
// 3-stage cp.async pipeline, ONE __syncthreads per chunk.
// R15: __launch_bounds__(256, 2) pins regs <= 128 — R14's 132 regs crossed
// the 32K-regs/CTA cliff (64K regfile) and halved occupancy to 1 CTA/SM.
// Smem 110592 B x 2 CTAs = 216 KB <= 227 KB: fits.
// ---------------------------------------------------------------------------
#define KSW 36
#define TILE_WORDS (128 * KSW)
#define GEMM_SMEM (6 * TILE_WORDS * 4)   // 110592 B

__global__ __launch_bounds__(256, 2) void gemm_bf16_qkv(
    const __nv_bfloat16* __restrict__ A0, const __nv_bfloat16* __restrict__ A1,
    const __nv_bfloat16* __restrict__ A2,
    const __nv_bfloat16* __restrict__ B0, const __nv_bfloat16* __restrict__ B1,
    const __nv_bfloat16* __restrict__ B2,
    __nv_bfloat16* __restrict__ C0, __nv_bfloat16* __restrict__ C1,
    __nv_bfloat16* __restrict__ C2, int M, int N, int K)
{
    extern __shared__ uint32_t shw[];

    const int z = blockIdx.z;
    const __nv_bfloat16* A = (z == 0) ? A0 : (z == 1) ? A1 : A2;
    const __nv_bfloat16* Bt = (z == 0) ? B0 : (z == 1) ? B1 : B2;
    __nv_bfloat16* C = (z == 0) ? C0 : (z == 1) ? C1 : C2;

    const int tid = threadIdx.x;
    const int wid = tid >> 5;
    const int lane = tid & 31;
    const int mb = (wid & 3) * 32;
    const int nb = (wid >> 2) * 64;
    const int g = lane >> 2;
    const int t = lane & 3;
    const int m0 = blockIdx.y * 128;
    const int n0 = blockIdx.x * 128;

    const int quad = lane >> 3;
    const int within = lane & 7;
    const int arow = (quad & 1) * 8 + within;
    const int acol = (quad >> 1) * 4;
    const int brow = (quad >> 1) * 8 + within;
    const int bcol = (quad & 1) * 4;

    const uint32_t aoff0 = (uint32_t)((mb + arow) * KSW + acol) * 4u;
    const uint32_t aoff1 = (uint32_t)((mb + 16 + arow) * KSW + acol) * 4u;
    uint32_t boff[4];
#pragma unroll
    for (int ntp = 0; ntp < 4; ntp++)
        boff[ntp] = (uint32_t)((nb + ntp * 16 + brow) * KSW + bcol) * 4u;

    uint32_t saw[3], sbw[3];
#pragma unroll
    for (int s = 0; s < 3; s++) {
        saw[s] = smem_u32(shw + s * TILE_WORDS);
        sbw[s] = smem_u32(shw + (3 + s) * TILE_WORDS);
    }

    float acc[2][8][4];
#pragma unroll
    for (int i = 0; i < 2; i++)
#pragma unroll
        for (int j = 0; j < 8; j++)
#pragma unroll
            for (int q = 0; q < 4; q++) acc[i][j][q] = 0.f;

    const int NCH = K / 64;

    auto issue = [&](int c, int b) {
        const __nv_bfloat16* Ag = A + (size_t)m0 * K + (size_t)c * 64;
        const __nv_bfloat16* Bg = Bt + (size_t)n0 * K + (size_t)c * 64;
#pragma unroll
        for (int i = 0; i < 4; i++) {
            const int u = tid + 256 * i;
            const int row = u >> 3;
            const int seg = u & 7;
            const uint32_t so = (uint32_t)(row * KSW + seg * 4) * 4u;
            cp_async16(saw[b] + so, Ag + (size_t)row * K + seg * 8);
            cp_async16(sbw[b] + so, Bg + (size_t)row * K + seg * 8);
        }
        CP_COMMIT();
    };

    issue(0, 0);
    issue(1, 1);

    int b = 0, bn = 2;   // compute buffer, next-fill buffer (avoid % in loop)
    for (int c = 0; c < NCH; c++) {
        CP_WAIT1();
        __syncthreads();            // chunk c visible; buffer bn retired
        if (c + 2 < NCH) issue(c + 2, bn);
        else CP_COMMIT();
#pragma unroll
        for (int s = 0; s < 4; s++) {
            const uint32_t ks = (uint32_t)s * 32u;
            uint32_t af0[4], af1[4];
            ldsm_x4(af0, saw[b] + aoff0 + ks);
            ldsm_x4(af1, saw[b] + aoff1 + ks);
#pragma unroll
            for (int ntp = 0; ntp < 4; ntp++) {
                uint32_t bq[4];
                ldsm_x4(bq, sbw[b] + boff[ntp] + ks);
                mma_bf16(acc[0][2 * ntp],     af0, bq);
                mma_bf16(acc[1][2 * ntp],     af1, bq);
                mma_bf16(acc[0][2 * ntp + 1], af0, bq + 2);
                mma_bf16(acc[1][2 * ntp + 1], af1, bq + 2);
            }
        }
        b = (b == 2) ? 0 : b + 1;
        bn = (bn == 2) ? 0 : bn + 1;
    }

#pragma unroll
    for (int mt = 0; mt < 2; mt++) {
        const int r = m0 + mb + mt * 16 + g;
#pragma unroll
        for (int nt = 0; nt < 8; nt++) {
            const int cx = n0 + nb + nt * 8 + 2 * t;
            uint32_t w0 = pack_bf16x2(acc[mt][nt][0], acc[mt][nt][1]);
            uint32_t w1 = pack_bf16x2(acc[mt][nt][2], acc[mt][nt][3]);
            *reinterpret_cast<uint32_t*>(C + (size_t)r * N + cx) = w0;
            *reinterpret_cast<uint32_t*>(C + (size_t)(r + 8) * N + cx) = w1;
        }
    }
}

__global__ __launch_bounds__(256, 2) void gemm_bf16_out(
    const __nv_bfloat16* __restrict__ A, const __nv_bfloat16* __restrict__ Bt,
    const float* __restrict__ bias, float* __restrict__ C,
    int M, int N, int K)
{
    extern __shared__ uint32_t shw[];

    const int tid = threadIdx.x;
    const int wid = tid >> 5;
    const int lane = tid & 31;
    const int mb = (wid & 3) * 32;
    const int nb = (wid >> 2) * 64;
    const int g = lane >> 2;
    const int t = lane & 3;
    const int m0 = blockIdx.y * 128;
    const int n0 = blockIdx.x * 128;

    const int quad = lane >> 3;
    const int within = lane & 7;
    const int arow = (quad & 1) * 8 + within;
    const int acol = (quad >> 1) * 4;
    const int brow = (quad >> 1) * 8 + within;
    const int bcol = (quad & 1) * 4;

    const uint32_t aoff0 = (uint32_t)((mb + arow) * KSW + acol) * 4u;
    const uint32_t aoff1 = (uint32_t)((mb + 16 + arow) * KSW + acol) * 4u;
    uint32_t boff[4];
#pragma unroll
    for (int ntp = 0; ntp < 4; ntp++)
        boff[ntp] = (uint32_t)((nb + ntp * 16 + brow) * KSW + bcol) * 4u;

    uint32_t saw[3], sbw[3];
#pragma unroll
    for (int s = 0; s < 3; s++) {
        saw[s] = smem_u32(shw + s * TILE_WORDS);
        sbw[s] = smem_u32(shw + (3 + s) * TILE_WORDS);
    }

    float acc[2][8][4];
#pragma unroll
    for (int i = 0; i < 2; i++)
#pragma unroll
        for (int j = 0; j < 8; j++)
#pragma unroll
            for (int q = 0; q < 4; q++) acc[i][j][q] = 0.f;

    const int NCH = K / 64;

    auto issue = [&](int c, int b) {
        const __nv_bfloat16* Ag = A + (size_t)m0 * K + (size_t)c * 64;
        const __nv_bfloat16* Bg = Bt + (size_t)n0 * K + (size_t)c * 64;
#pragma unroll
        for (int i = 0; i < 4; i++) {
            const int u = tid + 256 * i;
            const int row = u >> 3;
            const int seg = u & 7;
            const uint32_t so = (uint32_t)(row * KSW + seg * 4) * 4u;
            cp_async16(saw[b] + so, Ag + (size_t)row * K + seg * 8);
            cp_async16(sbw[b] + so, Bg + (size_t)row * K + seg * 8);
        }
        CP_COMMIT();
    };

    issue(0, 0);
    issue(1, 1);

    int b = 0, bn = 2;
    for (int c = 0; c < NCH; c++) {
        CP_WAIT1();
        __syncthreads();
        if (c + 2 < NCH) issue(c + 2, bn);
        else CP_COMMIT();
#pragma unroll
        for (int s = 0; s < 4; s++) {
            const uint32_t ks = (uint32_t)s * 32u;
            uint32_t af0[4], af1[4];
            ldsm_x4(af0, saw[b] + aoff0 + ks);
            ldsm_x4(af1, saw[b] + aoff1 + ks);
#pragma unroll
            for (int ntp = 0; ntp < 4; ntp++) {
                uint32_t bq[4];
                ldsm_x4(bq, sbw[b] + boff[ntp] + ks);
                mma_bf16(acc[0][2 * ntp],     af0, bq);
                mma_bf16(acc[1][2 * ntp],     af1, bq);
                mma_bf16(acc[0][2 * ntp + 1], af0, bq + 2);
                mma_bf16(acc[1][2 * ntp + 1], af1, bq + 2);
            }
        }
        b = (b == 2) ? 0 : b + 1;
        bn = (bn == 2) ? 0 : bn + 1;
    }

#pragma unroll
    for (int mt = 0; mt < 2; mt++) {
        const int r = m0 + mb + mt * 16 + g;
#pragma unroll
        for (int nt = 0; nt < 8; nt++) {
            const int cx = n0 + nb + nt * 8 + 2 * t;
            const float b0 = __ldg(&bias[cx]);
            const float b1 = __ldg(&bias[cx + 1]);
            float2 v0, v1;
            v0.x = acc[mt][nt][0] + b0; v0.y = acc[mt][nt][1] + b1;
            v1.x = acc[mt][nt][2] + b0; v1.y = acc[mt][nt][3] + b1;
            *(float2*)(C + (size_t)r * N + cx) = v0;
            *(float2*)(C + (size_t)(r + 8) * N + cx) = v1;
        }
    }
}

// ---------------------------------------------------------------------------
// bf16 HMMA flash attention. P in registers (R12), packed-bit mask (R13),
// 3-stage K/V pipeline with one __syncthreads per tile (R14), and
// __launch_bounds__(256, 2) pinning regs <= 128 (R15).
// ---------------------------------------------------------------------------
#define AKW 36
#define ATT_TILE (64 * AKW)
#define ATT_SMEM (6 * ATT_TILE * 4)   // 55296 B

__global__ __launch_bounds__(256, 2) void attn_bf16(
    const __nv_bfloat16* __restrict__ Q, const __nv_bfloat16* __restrict__ K,
    const __nv_bfloat16* __restrict__ VT,
    const unsigned long long* __restrict__ maskbits,
    __nv_bfloat16* __restrict__ O)
{
    extern __shared__ uint32_t smw[];

    const int tid = threadIdx.x;
    const int wid = tid >> 5;
    const int lane = tid & 31;
    const int gq = lane >> 2;
    const int t = lane & 3;
    const int qb = blockIdx.x;
    const int grp = blockIdx.y;
    const int r0 = wid * 16;

    const int quad = lane >> 3;
    const int within = lane & 7;
    const int arow = (quad & 1) * 8 + within;
    const int acol = (quad >> 1) * 4;
    const int brow = (quad >> 1) * 8 + within;
    const int bcol = (quad & 1) * 4;

    uint32_t boffA[4];
#pragma unroll
    for (int ntp = 0; ntp < 4; ntp++)
        boffA[ntp] = (uint32_t)((ntp * 16 + brow) * AKW + bcol) * 4u;

    uint32_t skw[3], svw[3];
#pragma unroll
    for (int s = 0; s < 3; s++) {
        skw[s] = smem_u32(smw + s * ATT_TILE);
        svw[s] = smem_u32(smw + (3 + s) * ATT_TILE);
    }

    const __nv_bfloat16* Qg = Q + ((size_t)grp * SLEN + qb * 128 + r0) * HEADDIM;
    const __nv_bfloat16* Kg = K + (size_t)grp * SLEN * HEADDIM;
    const __nv_bfloat16* VTg = VT + (size_t)grp * SLEN * HEADDIM;
    const unsigned long long* mw =
        maskbits + ((size_t)(grp % BATCH) * SLEN + (size_t)(qb * 128 + r0)) * (SLEN / 64);

    auto issue = [&](int kt, int b) {
#pragma unroll
        for (int i = 0; i < 2; i++) {
            const int u = tid + 256 * i;
            const int row = u >> 3;
            const int seg = u & 7;
            const uint32_t so = (uint32_t)(row * AKW + seg * 4) * 4u;
            cp_async16(skw[b] + so, Kg + (size_t)(kt * 64 + row) * HEADDIM + seg * 8);
            cp_async16(svw[b] + so, VTg + (size_t)row * SLEN + kt * 64 + seg * 8);
        }
        CP_COMMIT();
    };

    // ---- Stage Q through tile buffers, build persistent A fragments
    uint32_t* sQw = smw + r0 * AKW;
    const uint32_t sq_addr = smem_u32(sQw) + (uint32_t)(arow * AKW + acol) * 4u;
    {
        const int row = lane >> 1;
        const int cs = (lane & 1) * 16;
#pragma unroll
        for (int j = 0; j < 4; j++) {
            uint4 v = *(const uint4*)(Qg + (size_t)row * HEADDIM + (cs + j * 4) * 2);
            *(uint4*)&sQw[row * AKW + cs + j * 4] = v;
        }
    }
    __syncwarp();
    uint32_t qf[4][4];
#pragma unroll
    for (int s = 0; s < 4; s++)
        ldsm_x4(qf[s], sq_addr + (uint32_t)s * 32u);
    __syncthreads();

    issue(0, 0);
    issue(1, 1);

    float oacc[8][4];
#pragma unroll
    for (int nt = 0; nt < 8; nt++)
#pragma unroll
        for (int q = 0; q < 4; q++) oacc[nt][q] = 0.f;
    float mA = -INFINITY, mB = -INFINITY, lA = 0.f, lB = 0.f;

    const float scale = 0.125f;
    const int NT = SLEN / 64;

    int b = 0, bn = 2;
    for (int kt = 0; kt < NT; kt++) {
        CP_WAIT1();
        __syncthreads();
        if (kt + 2 < NT) issue(kt + 2, bn);
        else CP_COMMIT();

        // ---- S = Q K^T
        float sacc[8][4];
#pragma unroll
        for (int nt = 0; nt < 8; nt++)
#pragma unroll
            for (int q = 0; q < 4; q++) sacc[nt][q] = 0.f;
#pragma unroll
        for (int s = 0; s < 4; s++) {
            const uint32_t ks = (uint32_t)s * 32u;
#pragma unroll
            for (int ntp = 0; ntp < 4; ntp++) {
                uint32_t bq[4];
                ldsm_x4(bq, skw[b] + boffA[ntp] + ks);
                mma_bf16(sacc[2 * ntp],     qf[s], bq);
                mma_bf16(sacc[2 * ntp + 1], qf[s], bq + 2);
            }
        }

        // ---- Mask + scale (packed bits, warp-uniform fast path)
        const unsigned long long wA = mw[(size_t)gq * (SLEN / 64) + kt];
        const unsigned long long wB = mw[(size_t)(gq + 8) * (SLEN / 64) + kt];
        if (__all_sync(0xffffffffu, (wA | wB) == 0ull)) {
#pragma unroll
            for (int nt = 0; nt < 8; nt++) {
                sacc[nt][0] *= scale; sacc[nt][1] *= scale;
                sacc[nt][2] *= scale; sacc[nt][3] *= scale;
            }
        } else {
#pragma unroll
            for (int nt = 0; nt < 8; nt++) {
                const int c0 = nt * 8 + 2 * t;
                sacc[nt][0] = ((wA >> c0) & 1ull) ? -1e9f : sacc[nt][0] * scale;
                sacc[nt][1] = ((wA >> (c0 + 1)) & 1ull) ? -1e9f : sacc[nt][1] * scale;
                sacc[nt][2] = ((wB >> c0) & 1ull) ? -1e9f : sacc[nt][2] * scale;
                sacc[nt][3] = ((wB >> (c0 + 1)) & 1ull) ? -1e9f : sacc[nt][3] * scale;
            }
        }

        // ---- Online softmax
        float mxA = -INFINITY, mxB = -INFINITY;
#pragma unroll
        for (int nt = 0; nt < 8; nt++) {
            mxA = fmaxf(mxA, fmaxf(sacc[nt][0], sacc[nt][1]));
            mxB = fmaxf(mxB, fmaxf(sacc[nt][2], sacc[nt][3]));
        }
        mxA = fmaxf(mxA, __shfl_xor_sync(0xffffffffu, mxA, 1));
        mxA = fmaxf(mxA, __shfl_xor_sync(0xffffffffu, mxA, 2));
        mxB = fmaxf(mxB, __shfl_xor_sync(0xffffffffu, mxB, 1));
        mxB = fmaxf(mxB, __shfl_xor_sync(0xffffffffu, mxB, 2));

        const float mnA = fmaxf(mA, mxA);
        const float mnB = fmaxf(mB, mxB);
        const float cA = __expf(mA - mnA);
        const float cB = __expf(mB - mnB);
        float suA = 0.f, suB = 0.f;
#pragma unroll
        for (int nt = 0; nt < 8; nt++) {
            sacc[nt][0] = __expf(sacc[nt][0] - mnA);
            sacc[nt][1] = __expf(sacc[nt][1] - mnA);
            sacc[nt][2] = __expf(sacc[nt][2] - mnB);
            sacc[nt][3] = __expf(sacc[nt][3] - mnB);
            suA += sacc[nt][0] + sacc[nt][1];
            suB += sacc[nt][2] + sacc[nt][3];
        }
        suA += __shfl_xor_sync(0xffffffffu, suA, 1);
        suA += __shfl_xor_sync(0xffffffffu, suA, 2);
        suB += __shfl_xor_sync(0xffffffffu, suB, 1);
        suB += __shfl_xor_sync(0xffffffffu, suB, 2);
        lA = lA * cA + suA;
        lB = lB * cB + suB;
        mA = mnA;
        mB = mnB;
#pragma unroll
        for (int nt = 0; nt < 8; nt++) {
            oacc[nt][0] *= cA; oacc[nt][1] *= cA;
            oacc[nt][2] *= cB; oacc[nt][3] *= cB;
        }

        // ---- P A-fragments direct from registers (R12-validated mapping)
        uint32_t pf[4][4];
#pragma unroll
        for (int s = 0; s < 4; s++) {
            pf[s][0] = pack_bf16x2(sacc[2 * s][0],     sacc[2 * s][1]);
            pf[s][1] = pack_bf16x2(sacc[2 * s][2],     sacc[2 * s][3]);
            pf[s][2] = pack_bf16x2(sacc[2 * s + 1][0], sacc[2 * s + 1][1]);
            pf[s][3] = pack_bf16x2(sacc[2 * s + 1][2], sacc[2 * s + 1][3]);
        }

        // ---- O += P V
#pragma unroll
        for (int s = 0; s < 4; s++) {
            const uint32_t ks = (uint32_t)s * 32u;
#pragma unroll
            for (int ntp = 0; ntp < 4; ntp++) {
                uint32_t bq[4];
                ldsm_x4(bq, svw[b] + boffA[ntp] + ks);
                mma_bf16(oacc[2 * ntp],     pf[s], bq);
                mma_bf16(oacc[2 * ntp + 1], pf[s], bq + 2);
            }
        }
        b = (b == 2) ? 0 : b + 1;
        bn = (bn == 2) ? 0 : bn + 1;
    }

    // ---- Normalize + write O as bf16
    const float iA = 1.f / lA;
    const float iB = 1.f / lB;
    __nv_bfloat16* Og = O + ((size_t)grp * SLEN + qb * 128 + r0) * HEADDIM;
#pragma unroll
    for (int nt = 0; nt < 8; nt++) {
        const int cb = nt * 8 + 2 * t;
        uint32_t wA = pack_bf16x2(oacc[nt][0] * iA, oacc[nt][1] * iA);
        uint32_t wB = pack_bf16x2(oacc[nt][2] * iB, oacc[nt][3] * iB);
        *reinterpret_cast<uint32_t*>(Og + (size_t)gq * HEADDIM + cb) = wA;
        *reinterpret_cast<uint32_t*>(Og + (size_t)(gq + 8) * HEADDIM + cb) = wB;
    }
}

// ---------------------------------------------------------------------------
// Fused residual + LayerNorm (unchanged)
// ---------------------------------------------------------------------------
__global__ __launch_bounds__(256) void ln_kernel(
    const float* __restrict__ x, const float* __restrict__ p,
    const float* __restrict__ gamma, const float* __restrict__ beta,
    float* __restrict__ out)
{
    const int row = blockIdx.x;
    const int t = threadIdx.x;
    const size_t base = (size_t)row * DMODEL + t * 4;

    float4 xv = *(const float4*)(x + base);
    float4 pv = *(const float4*)(p + base);
    float v0 = xv.x + pv.x, v1 = xv.y + pv.y, v2 = xv.z + pv.z, v3 = xv.w + pv.w;

    __shared__ float red[8];
    float s = v0 + v1 + v2 + v3;
#pragma unroll
    for (int off = 16; off >= 1; off >>= 1) s += __shfl_xor_sync(0xffffffffu, s, off);
    if ((t & 31) == 0) red[t >> 5] = s;
    __syncthreads();
    float mu = (red[0] + red[1] + red[2] + red[3] +
                red[4] + red[5] + red[6] + red[7]) * (1.f / DMODEL);
    __syncthreads();

    float d0 = v0 - mu, d1 = v1 - mu, d2 = v2 - mu, d3 = v3 - mu;
    float q = d0 * d0 + d1 * d1 + d2 * d2 + d3 * d3;
#pragma unroll
    for (int off = 16; off >= 1; off >>= 1) q += __shfl_xor_sync(0xffffffffu, q, off);
    if ((t & 31) == 0) red[t >> 5] = q;
    __syncthreads();
    float var = (red[0] + red[1] + red[2] + red[3] +
                 red[4] + red[5] + red[6] + red[7]) * (1.f / DMODEL);
    float rs = rsqrtf(var + 1e-5f);

    float4 gv = *(const float4*)(gamma + t * 4);
    float4 bv = *(const float4*)(beta + t * 4);
    float4 ov;
    ov.x = d0 * rs * gv.x + bv.x;
    ov.y = d1 * rs * gv.y + bv.y;
    ov.z = d2 * rs * gv.z + bv.z;
    ov.w = d3 * rs * gv.w + bv.w;
    *(float4*)(out + base) = ov;
}

// ---------------------------------------------------------------------------
// Launch
// ---------------------------------------------------------------------------
extern "C" void kernel_launch(void* const* d_in, const int* in_sizes, int n_in,
                              void* d_out, int out_size)
{
    (void)in_sizes; (void)n_in; (void)out_size;
    const float* q_in  = (const float*)d_in[0];
    const float* k_in  = (const float*)d_in[1];
    const float* v_in  = (const float*)d_in[2];
    const unsigned char* mask = (const unsigned char*)d_in[3];
    const float* Wq = (const float*)d_in[4];
    const float* Wk = (const float*)d_in[5];
    const float* Wv = (const float*)d_in[6];
    const float* Wo = (const float*)d_in[7];
    const float* bo = (const float*)d_in[8];
    const float* gamma = (const float*)d_in[9];
    const float* beta  = (const float*)d_in[10];
    float* out = (float*)d_out;

    float* pP;
    __nv_bfloat16 *pQb, *pKb, *pVb, *pVTb, *pOb, *pQin, *pKin, *pVin;
    __nv_bfloat16 *pWqT, *pWkT, *pWvT, *pWoT;
    unsigned long long* pMb;
    cudaGetSymbolAddress((void**)&pP, g_P);
    cudaGetSymbolAddress((void**)&pQb, g_Qb);
    cudaGetSymbolAddress((void**)&pKb, g_Kb);
    cudaGetSymbolAddress((void**)&pVb, g_Vb);
    cudaGetSymbolAddress((void**)&pVTb, g_VTb);
    cudaGetSymbolAddress((void**)&pOb, g_Ob);
    cudaGetSymbolAddress((void**)&pQin, g_Qin);
    cudaGetSymbolAddress((void**)&pKin, g_Kin);
    cudaGetSymbolAddress((void**)&pVin, g_Vin);
    cudaGetSymbolAddress((void**)&pWqT, g_WqT);
    cudaGetSymbolAddress((void**)&pWkT, g_WkT);
    cudaGetSymbolAddress((void**)&pWvT, g_WvT);
    cudaGetSymbolAddress((void**)&pWoT, g_WoT);
    cudaGetSymbolAddress((void**)&pMb, g_Mb);

    cudaFuncSetAttribute(gemm_bf16_qkv, cudaFuncAttributeMaxDynamicSharedMemorySize, GEMM_SMEM);
    cudaFuncSetAttribute(gemm_bf16_out, cudaFuncAttributeMaxDynamicSharedMemorySize, GEMM_SMEM);
    cudaFuncSetAttribute(attn_bf16, cudaFuncAttributeMaxDynamicSharedMemorySize, ATT_SMEM);

    // launch 0: fused weight transposes
    dim3 tgrid(DMODEL / 32, DMODEL / 32, 4);
    dim3 tblk(32, 8);
    transpose1024_bf16_fused<<<tgrid, tblk>>>(Wq, Wk, Wv, Wo, pWqT, pWkT, pWvT, pWoT);

    // launch 1: fused input conversion
    dim3 cgrid(NROWS * DMODEL / (256 * 8), 3);
    cvt_bf16_fused<<<cgrid, 256>>>(q_in, k_in, v_in, pQin, pKin, pVin);

    // launch 2: mask bit-pack
    mask_pack<<<BATCH * SLEN * (SLEN / 64) / 256, 256>>>(mask, pMb);

    // launch 3: batched Q/K/V projections
    dim3 ggrid3(DMODEL / 128, NROWS / 128, 3);
    gemm_bf16_qkv<<<ggrid3, 256, GEMM_SMEM>>>(
        pQin, pKin, pVin, pWqT, pWkT, pWvT, pQb, pKb, pVb,
        NROWS, DMODEL, DMODEL);

    // launch 4: V -> VT per group
    dim3 vgrid(SLEN / 32, HEADDIM / 32, NGROUPS);
    vtranspose_bf16<<<vgrid, tblk>>>(pVb, pVTb);

    // launch 5: attention
    dim3 agrid(SLEN / 128, NGROUPS);
    attn_bf16<<<agrid, 256, ATT_SMEM>>>(pQb, pKb, pVTb, pMb, pOb);

    // launch 6: output projection (+bias, fp32 out)
    dim3 ggrid1(DMODEL / 128, NROWS / 128);
    gemm_bf16_out<<<ggrid1, 256, GEMM_SMEM>>>(pOb, pWoT, bo, pP, NROWS, DMODEL, DMODEL);

    // launch 7: residual + LayerNorm
    ln_kernel<<<NROWS, 256>>>(q_in, pP, gamma, beta, out);
}

// round 16
// speedup vs baseline: 1.2296x; 1.0154x over previous
#include <cuda_runtime.h>
#include <cuda_bf16.h>
#include <math.h>
#include <cstdint>

// Problem constants
#define BATCH   2
#define SLEN    2048
#define DMODEL  1024
#define NHEADS  16
#define HEADDIM 64
#define NROWS   (BATCH * SLEN)      // 4096
#define NGROUPS (BATCH * NHEADS)    // 32 reshaped "heads"

// Scratch (allocation-free rule: __device__ globals)
__device__ float g_P[NROWS * DMODEL];
__device__ __nv_bfloat16 g_Qb[NROWS * DMODEL];
__device__ __nv_bfloat16 g_Kb[NROWS * DMODEL];
__device__ __nv_bfloat16 g_Vb[NROWS * DMODEL];
__device__ __nv_bfloat16 g_VTb[NROWS * DMODEL];  // per-group transposed V
__device__ __nv_bfloat16 g_Ob[NROWS * DMODEL];
__device__ __nv_bfloat16 g_Qin[NROWS * DMODEL];
__device__ __nv_bfloat16 g_Kin[NROWS * DMODEL];
__device__ __nv_bfloat16 g_Vin[NROWS * DMODEL];
__device__ __nv_bfloat16 g_WqT[DMODEL * DMODEL];
__device__ __nv_bfloat16 g_WkT[DMODEL * DMODEL];
__device__ __nv_bfloat16 g_WvT[DMODEL * DMODEL];
__device__ __nv_bfloat16 g_WoT[DMODEL * DMODEL];
__device__ unsigned long long g_Mb[BATCH * SLEN * (SLEN / 64)];  // packed mask bits

// ---------------------------------------------------------------------------
// Helpers (sm_80+ only — compute_103 rejects 'a'-gated PTX like tcgen05)
// ---------------------------------------------------------------------------
__device__ __forceinline__ uint32_t smem_u32(const void* p) {
    uint32_t a;
    asm("{ .reg .u64 t; cvta.to.shared.u64 t, %1; cvt.u32.u64 %0, t; }"
        : "=r"(a) : "l"(p));
    return a;
}

__device__ __forceinline__ void cp_async16(uint32_t saddr, const void* gaddr) {
    asm volatile("cp.async.cg.shared.global [%0], [%1], 16;"
                 :: "r"(saddr), "l"(gaddr) : "memory");
}
#define CP_COMMIT() asm volatile("cp.async.commit_group;" ::: "memory")
#define CP_WAIT1()  asm volatile("cp.async.wait_group 1;" ::: "memory")

__device__ __forceinline__ void mma_bf16(float* d, const uint32_t* a, const uint32_t* b) {
    asm volatile(
        "mma.sync.aligned.m16n8k16.row.col.f32.bf16.bf16.f32 "
        "{%0,%1,%2,%3}, {%4,%5,%6,%7}, {%8,%9}, {%0,%1,%2,%3};"
        : "+f"(d[0]), "+f"(d[1]), "+f"(d[2]), "+f"(d[3])
        : "r"(a[0]), "r"(a[1]), "r"(a[2]), "r"(a[3]), "r"(b[0]), "r"(b[1]));
}

__device__ __forceinline__ void ldsm_x4(uint32_t* r, uint32_t saddr) {
    asm volatile("ldmatrix.sync.aligned.m8n8.x4.shared.b16 {%0,%1,%2,%3}, [%4];"
                 : "=r"(r[0]), "=r"(r[1]), "=r"(r[2]), "=r"(r[3]) : "r"(saddr));
}

__device__ __forceinline__ uint32_t pack_bf16x2(float lo, float hi) {
    __nv_bfloat162 h = __floats2bfloat162_rn(lo, hi);
    return *reinterpret_cast<uint32_t*>(&h);
}

// ---------------------------------------------------------------------------
// Fused prep kernel: weight transposes (blocks 0..4095), input cvt
// (blocks 4096..10239), mask bit-pack (blocks 10240..10751). The three
// phases are independent; one launch lets them overlap across SMs.
// Bodies byte-identical to the R13/R15-validated kernels.
// ---------------------------------------------------------------------------
#define PREP_WT_BLOCKS   4096     // 32 x 32 x 4
#define PREP_CVT_BLOCKS  6144     // 2048 x 3
#define PREP_MB_BLOCKS   512
#define PREP_BLOCKS (PREP_WT_BLOCKS + PREP_CVT_BLOCKS + PREP_MB_BLOCKS)

__global__ __launch_bounds__(256) void prep_fused(
    const float* __restrict__ W0, const float* __restrict__ W1,
    const float* __restrict__ W2, const float* __restrict__ W3,
    __nv_bfloat16* __restrict__ T0, __nv_bfloat16* __restrict__ T1,
    __nv_bfloat16* __restrict__ T2, __nv_bfloat16* __restrict__ T3,
    const float* __restrict__ x0, const float* __restrict__ x1,
    const float* __restrict__ x2,
    __nv_bfloat16* __restrict__ y0, __nv_bfloat16* __restrict__ y1,
    __nv_bfloat16* __restrict__ y2,
    const unsigned char* __restrict__ m, unsigned long long* __restrict__ mb)
{
    const int bid = blockIdx.x;
    const int tid = threadIdx.x;

    if (bid < PREP_WT_BLOCKS) {
        // ---- weight transpose: Wt[n][k] = bf16(W[k][n])
        __shared__ float t[32][33];
        const int z = bid >> 10;            // 0..3
        const int rem = bid & 1023;
        const int bx = (rem & 31) * 32;
        const int by = (rem >> 5) * 32;
        const float* W = (z == 0) ? W0 : (z == 1) ? W1 : (z == 2) ? W2 : W3;
        __nv_bfloat16* Wt = (z == 0) ? T0 : (z == 1) ? T1 : (z == 2) ? T2 : T3;
        const int x = tid & 31;
        const int y = tid >> 5;             // 0..7
#pragma unroll
        for (int i = 0; i < 32; i += 8)
            t[y + i][x] = W[(size_t)(by + y + i) * DMODEL + bx + x];
        __syncthreads();
#pragma unroll
        for (int i = 0; i < 32; i += 8)
            Wt[(size_t)(bx + y + i) * DMODEL + by + x] = __float2bfloat16_rn(t[x][y + i]);
    } else if (bid < PREP_WT_BLOCKS + PREP_CVT_BLOCKS) {
        // ---- fp32 -> bf16 input conversion (8 elements/thread)
        const int i0 = bid - PREP_WT_BLOCKS;
        const int z = i0 / 2048;
        const int blk = i0 % 2048;
        const float* x = (z == 0) ? x0 : (z == 1) ? x1 : x2;
        __nv_bfloat16* y = (z == 0) ? y0 : (z == 1) ? y1 : y2;
        const size_t i = ((size_t)blk * 256 + tid) * 8;
        float4 a = *(const float4*)(x + i);
        float4 b = *(const float4*)(x + i + 4);
        __nv_bfloat162* yp = reinterpret_cast<__nv_bfloat162*>(y + i);
        yp[0] = __floats2bfloat162_rn(a.x, a.y);
        yp[1] = __floats2bfloat162_rn(a.z, a.w);
        yp[2] = __floats2bfloat162_rn(b.x, b.y);
        yp[3] = __floats2bfloat162_rn(b.z, b.w);
    } else {
        // ---- mask bit-pack: one uint64 per (row, 64-key word)
        const int blk = bid - PREP_WT_BLOCKS - PREP_CVT_BLOCKS;
        const int idx = blk * 256 + tid;
        const uint4* p4 = reinterpret_cast<const uint4*>(m + (size_t)idx * 64);
        unsigned long long w = 0;
#pragma unroll
        for (int q = 0; q < 4; q++) {
            uint4 v = p4[q];
            uint32_t b = ((v.x * 0x01020408u) >> 24) & 0xFu;
            b |= (((v.y * 0x01020408u) >> 24) & 0xFu) << 4;
            b |= (((v.z * 0x01020408u) >> 24) & 0xFu) << 8;
            b |= (((v.w * 0x01020408u) >> 24) & 0xFu) << 12;
            w |= (unsigned long long)b << (q * 16);
        }
        mb[idx] = w;
    }
}

// ---------------------------------------------------------------------------
// V transpose per group (bf16): V[g][s][d] -> VT[g][d][s]
// ---------------------------------------------------------------------------
__global__ __launch_bounds__(256) void vtranspose_bf16(
    const __nv_bfloat16* __restrict__ V, __nv_bfloat16* __restrict__ VT)
{
    __shared__ __nv_bfloat16 t[32][34];
    const int g = blockIdx.z;
    const int s0 = blockIdx.x * 32, d0 = blockIdx.y * 32;
    const int x = threadIdx.x, y = threadIdx.y;
    const __nv_bfloat16* Vg = V + (size_t)g * SLEN * HEADDIM;
    __nv_bfloat16* VTg = VT + (size_t)g * SLEN * HEADDIM;
#pragma unroll
    for (int i = 0; i < 32; i += 8)
        t[y + i][x] = Vg[(size_t)(s0 + y + i) * HEADDIM + d0 + x];
    __syncthreads();
#pragma unroll
    for (int i = 0; i < 32; i += 8)
        VTg[(size_t)(d0 + y + i) * SLEN + s0 + x] = t[x][y + i];
}

// ---------------------------------------------------------------------------
// HMMA bf16 GEMM (R15-validated): CTA 128x128, BK=64, 8 warps (4x2),
// 3-stage cp.async, ONE __syncthreads per chunk, launch_bounds(256,2)
// pins regs <= 128 (2 CTAs/SM). Smem 110592 B x 2 = 216 KB <= 227 KB.
// ---------------------------------------------------------------------------
#define KSW 36
#define TILE_WORDS (128 * KSW)
#define GEMM_SMEM (6 * TILE_WORDS * 4)   // 110592 B

__global__ __launch_bounds__(256, 2) void gemm_bf16_qkv(
    const __nv_bfloat16* __restrict__ A0, const __nv_bfloat16* __restrict__ A1,
    const __nv_bfloat16* __restrict__ A2,
    const __nv_bfloat16* __restrict__ B0, const __nv_bfloat16* __restrict__ B1,
    const __nv_bfloat16* __restrict__ B2,
    __nv_bfloat16* __restrict__ C0, __nv_bfloat16* __restrict__ C1,
    __nv_bfloat16* __restrict__ C2, int M, int N, int K)
{
    extern __shared__ uint32_t shw[];

    const int z = blockIdx.z;
    const __nv_bfloat16* A = (z == 0) ? A0 : (z == 1) ? A1 : A2;
    const __nv_bfloat16* Bt = (z == 0) ? B0 : (z == 1) ? B1 : B2;
    __nv_bfloat16* C = (z == 0) ? C0 : (z == 1) ? C1 : C2;

    const int tid = threadIdx.x;
    const int wid = tid >> 5;
    const int lane = tid & 31;
    const int mb = (wid & 3) * 32;
    const int nb = (wid >> 2) * 64;
    const int g = lane >> 2;
    const int t = lane & 3;
    const int m0 = blockIdx.y * 128;
    const int n0 = blockIdx.x * 128;

    const int quad = lane >> 3;
    const int within = lane & 7;
    const int arow = (quad & 1) * 8 + within;
    const int acol = (quad >> 1) * 4;
    const int brow = (quad >> 1) * 8 + within;
    const int bcol = (quad & 1) * 4;

    const uint32_t aoff0 = (uint32_t)((mb + arow) * KSW + acol) * 4u;
    const uint32_t aoff1 = (uint32_t)((mb + 16 + arow) * KSW + acol) * 4u;
    uint32_t boff[4];
#pragma unroll
    for (int ntp = 0; ntp < 4; ntp++)
        boff[ntp] = (uint32_t)((nb + ntp * 16 + brow) * KSW + bcol) * 4u;

    uint32_t saw[3], sbw[3];
#pragma unroll
    for (int s = 0; s < 3; s++) {
        saw[s] = smem_u32(shw + s * TILE_WORDS);
        sbw[s] = smem_u32(shw + (3 + s) * TILE_WORDS);
    }

    float acc[2][8][4];
#pragma unroll
    for (int i = 0; i < 2; i++)
#pragma unroll
        for (int j = 0; j < 8; j++)
#pragma unroll
            for (int q = 0; q < 4; q++) acc[i][j][q] = 0.f;

    const int NCH = K / 64;

    auto issue = [&](int c, int b) {
        const __nv_bfloat16* Ag = A + (size_t)m0 * K + (size_t)c * 64;
        const __nv_bfloat16* Bg = Bt + (size_t)n0 * K + (size_t)c * 64;
#pragma unroll
        for (int i = 0; i < 4; i++) {
            const int u = tid + 256 * i;
            const int row = u >> 3;
            const int seg = u & 7;
            const uint32_t so = (uint32_t)(row * KSW + seg * 4) * 4u;
            cp_async16(saw[b] + so, Ag + (size_t)row * K + seg * 8);
            cp_async16(sbw[b] + so, Bg + (size_t)row * K + seg * 8);
        }
        CP_COMMIT();
    };

    issue(0, 0);
    issue(1, 1);

    int b = 0, bn = 2;
    for (int c = 0; c < NCH; c++) {
        CP_WAIT1();
        __syncthreads();
        if (c + 2 < NCH) issue(c + 2, bn);
        else CP_COMMIT();
#pragma unroll
        for (int s = 0; s < 4; s++) {
            const uint32_t ks = (uint32_t)s * 32u;
            uint32_t af0[4], af1[4];
            ldsm_x4(af0, saw[b] + aoff0 + ks);
            ldsm_x4(af1, saw[b] + aoff1 + ks);
#pragma unroll
            for (int ntp = 0; ntp < 4; ntp++) {
                uint32_t bq[4];
                ldsm_x4(bq, sbw[b] + boff[ntp] + ks);
                mma_bf16(acc[0][2 * ntp],     af0, bq);
                mma_bf16(acc[1][2 * ntp],     af1, bq);
                mma_bf16(acc[0][2 * ntp + 1], af0, bq + 2);
                mma_bf16(acc[1][2 * ntp + 1], af1, bq + 2);
            }
        }
        b = (b == 2) ? 0 : b + 1;
        bn = (bn == 2) ? 0 : bn + 1;
    }

#pragma unroll
    for (int mt = 0; mt < 2; mt++) {
        const int r = m0 + mb + mt * 16 + g;
#pragma unroll
        for (int nt = 0; nt < 8; nt++) {
            const int cx = n0 + nb + nt * 8 + 2 * t;
            uint32_t w0 = pack_bf16x2(acc[mt][nt][0], acc[mt][nt][1]);
            uint32_t w1 = pack_bf16x2(acc[mt][nt][2], acc[mt][nt][3]);
            *reinterpret_cast<uint32_t*>(C + (size_t)r * N + cx) = w0;
            *reinterpret_cast<uint32_t*>(C + (size_t)(r + 8) * N + cx) = w1;
        }
    }
}

__global__ __launch_bounds__(256, 2) void gemm_bf16_out(
    const __nv_bfloat16* __restrict__ A, const __nv_bfloat16* __restrict__ Bt,
    const float* __restrict__ bias, float* __restrict__ C,
    int M, int N, int K)
{
    extern __shared__ uint32_t shw[];

    const int tid = threadIdx.x;
    const int wid = tid >> 5;
    const int lane = tid & 31;
    const int mb = (wid & 3) * 32;
    const int nb = (wid >> 2) * 64;
    const int g = lane >> 2;
    const int t = lane & 3;
    const int m0 = blockIdx.y * 128;
    const int n0 = blockIdx.x * 128;

    const int quad = lane >> 3;
    const int within = lane & 7;
    const int arow = (quad & 1) * 8 + within;
    const int acol = (quad >> 1) * 4;
    const int brow = (quad >> 1) * 8 + within;
    const int bcol = (quad & 1) * 4;

    const uint32_t aoff0 = (uint32_t)((mb + arow) * KSW + acol) * 4u;
    const uint32_t aoff1 = (uint32_t)((mb + 16 + arow) * KSW + acol) * 4u;
    uint32_t boff[4];
#pragma unroll
    for (int ntp = 0; ntp < 4; ntp++)
        boff[ntp] = (uint32_t)((nb + ntp * 16 + brow) * KSW + bcol) * 4u;

    uint32_t saw[3], sbw[3];
#pragma unroll
    for (int s = 0; s < 3; s++) {
        saw[s] = smem_u32(shw + s * TILE_WORDS);
        sbw[s] = smem_u32(shw + (3 + s) * TILE_WORDS);
    }

    float acc[2][8][4];
#pragma unroll
    for (int i = 0; i < 2; i++)
#pragma unroll
        for (int j = 0; j < 8; j++)
#pragma unroll
            for (int q = 0; q < 4; q++) acc[i][j][q] = 0.f;

    const int NCH = K / 64;

    auto issue = [&](int c, int b) {
        const __nv_bfloat16* Ag = A + (size_t)m0 * K + (size_t)c * 64;
        const __nv_bfloat16* Bg = Bt + (size_t)n0 * K + (size_t)c * 64;
#pragma unroll
        for (int i = 0; i < 4; i++) {
            const int u = tid + 256 * i;
            const int row = u >> 3;
            const int seg = u & 7;
            const uint32_t so = (uint32_t)(row * KSW + seg * 4) * 4u;
            cp_async16(saw[b] + so, Ag + (size_t)row * K + seg * 8);
            cp_async16(sbw[b] + so, Bg + (size_t)row * K + seg * 8);
        }
        CP_COMMIT();
    };

    issue(0, 0);
    issue(1, 1);

    int b = 0, bn = 2;
    for (int c = 0; c < NCH; c++) {
        CP_WAIT1();
        __syncthreads();
        if (c + 2 < NCH) issue(c + 2, bn);
        else CP_COMMIT();
#pragma unroll
        for (int s = 0; s < 4; s++) {
            const uint32_t ks = (uint32_t)s * 32u;
            uint32_t af0[4], af1[4];
            ldsm_x4(af0, saw[b] + aoff0 + ks);
            ldsm_x4(af1, saw[b] + aoff1 + ks);
#pragma unroll
            for (int ntp = 0; ntp < 4; ntp++) {
                uint32_t bq[4];
                ldsm_x4(bq, sbw[b] + boff[ntp] + ks);
                mma_bf16(acc[0][2 * ntp],     af0, bq);
                mma_bf16(acc[1][2 * ntp],     af1, bq);
                mma_bf16(acc[0][2 * ntp + 1], af0, bq + 2);
                mma_bf16(acc[1][2 * ntp + 1], af1, bq + 2);
            }
        }
        b = (b == 2) ? 0 : b + 1;
        bn = (bn == 2) ? 0 : bn + 1;
    }

#pragma unroll
    for (int mt = 0; mt < 2; mt++) {
        const int r = m0 + mb + mt * 16 + g;
#pragma unroll
        for (int nt = 0; nt < 8; nt++) {
            const int cx = n0 + nb + nt * 8 + 2 * t;
            const float b0 = __ldg(&bias[cx]);
            const float b1 = __ldg(&bias[cx + 1]);
            float2 v0, v1;
            v0.x = acc[mt][nt][0] + b0; v0.y = acc[mt][nt][1] + b1;
            v1.x = acc[mt][nt][2] + b0; v1.y = acc[mt][nt][3] + b1;
            *(float2*)(C + (size_t)r * N + cx) = v0;
            *(float2*)(C + (size_t)(r + 8) * N + cx) = v1;
        }
    }
}

// ---------------------------------------------------------------------------
// bf16 HMMA flash attention (R15-validated). P in registers, packed-bit
// mask, 3-stage K/V pipeline, launch_bounds(256,2).
// ---------------------------------------------------------------------------
#define AKW 36
#define ATT_TILE (64 * AKW)
#define ATT_SMEM (6 * ATT_TILE * 4)   // 55296 B

__global__ __launch_bounds__(256, 2) void attn_bf16(
    const __nv_bfloat16* __restrict__ Q, const __nv_bfloat16* __restrict__ K,
    const __nv_bfloat16* __restrict__ VT,
    const unsigned long long* __restrict__ maskbits,
    __nv_bfloat16* __restrict__ O)
{
    extern __shared__ uint32_t smw[];

    const int tid = threadIdx.x;
    const int wid = tid >> 5;
    const int lane = tid & 31;
    const int gq = lane >> 2;
    const int t = lane & 3;
    const int qb = blockIdx.x;
    const int grp = blockIdx.y;
    const int r0 = wid * 16;

    const int quad = lane >> 3;
    const int within = lane & 7;
    const int arow = (quad & 1) * 8 + within;
    const int acol = (quad >> 1) * 4;
    const int brow = (quad >> 1) * 8 + within;
    const int bcol = (quad & 1) * 4;

    uint32_t boffA[4];
#pragma unroll
    for (int ntp = 0; ntp < 4; ntp++)
        boffA[ntp] = (uint32_t)((ntp * 16 + brow) * AKW + bcol) * 4u;

    uint32_t skw[3], svw[3];
#pragma unroll
    for (int s = 0; s < 3; s++) {
        skw[s] = smem_u32(smw + s * ATT_TILE);
        svw[s] = smem_u32(smw + (3 + s) * ATT_TILE);
    }

    const __nv_bfloat16* Qg = Q + ((size_t)grp * SLEN + qb * 128 + r0) * HEADDIM;
    const __nv_bfloat16* Kg = K + (size_t)grp * SLEN * HEADDIM;
    const __nv_bfloat16* VTg = VT + (size_t)grp * SLEN * HEADDIM;
    const unsigned long long* mw =
        maskbits + ((size_t)(grp % BATCH) * SLEN + (size_t)(qb * 128 + r0)) * (SLEN / 64);

    auto issue = [&](int kt, int b) {
#pragma unroll
        for (int i = 0; i < 2; i++) {
            const int u = tid + 256 * i;
            const int row = u >> 3;
            const int seg = u & 7;
            const uint32_t so = (uint32_t)(row * AKW + seg * 4) * 4u;
            cp_async16(skw[b] + so, Kg + (size_t)(kt * 64 + row) * HEADDIM + seg * 8);
            cp_async16(svw[b] + so, VTg + (size_t)row * SLEN + kt * 64 + seg * 8);
        }
        CP_COMMIT();
    };

    // ---- Stage Q through tile buffers, build persistent A fragments
    uint32_t* sQw = smw + r0 * AKW;
    const uint32_t sq_addr = smem_u32(sQw) + (uint32_t)(arow * AKW + acol) * 4u;
    {
        const int row = lane >> 1;
        const int cs = (lane & 1) * 16;
#pragma unroll
        for (int j = 0; j < 4; j++) {
            uint4 v = *(const uint4*)(Qg + (size_t)row * HEADDIM + (cs + j * 4) * 2);
            *(uint4*)&sQw[row * AKW + cs + j * 4] = v;
        }
    }
    __syncwarp();
    uint32_t qf[4][4];
#pragma unroll
    for (int s = 0; s < 4; s++)
        ldsm_x4(qf[s], sq_addr + (uint32_t)s * 32u);
    __syncthreads();

    issue(0, 0);
    issue(1, 1);

    float oacc[8][4];
#pragma unroll
    for (int nt = 0; nt < 8; nt++)
#pragma unroll
        for (int q = 0; q < 4; q++) oacc[nt][q] = 0.f;
    float mA = -INFINITY, mB = -INFINITY, lA = 0.f, lB = 0.f;

    const float scale = 0.125f;
    const int NT = SLEN / 64;

    int b = 0, bn = 2;
    for (int kt = 0; kt < NT; kt++) {
        CP_WAIT1();
        __syncthreads();
        if (kt + 2 < NT) issue(kt + 2, bn);
        else CP_COMMIT();

        // ---- S = Q K^T
        float sacc[8][4];
#pragma unroll
        for (int nt = 0; nt < 8; nt++)
#pragma unroll
            for (int q = 0; q < 4; q++) sacc[nt][q] = 0.f;
#pragma unroll
        for (int s = 0; s < 4; s++) {
            const uint32_t ks = (uint32_t)s * 32u;
#pragma unroll
            for (int ntp = 0; ntp < 4; ntp++) {
                uint32_t bq[4];
                ldsm_x4(bq, skw[b] + boffA[ntp] + ks);
                mma_bf16(sacc[2 * ntp],     qf[s], bq);
                mma_bf16(sacc[2 * ntp + 1], qf[s], bq + 2);
            }
        }

        // ---- Mask + scale (packed bits, warp-uniform fast path)
        const unsigned long long wA = mw[(size_t)gq * (SLEN / 64) + kt];
        const unsigned long long wB = mw[(size_t)(gq + 8) * (SLEN / 64) + kt];
        if (__all_sync(0xffffffffu, (wA | wB) == 0ull)) {
#pragma unroll
            for (int nt = 0; nt < 8; nt++) {
                sacc[nt][0] *= scale; sacc[nt][1] *= scale;
                sacc[nt][2] *= scale; sacc[nt][3] *= scale;
            }
        } else {
#pragma unroll
            for (int nt = 0; nt < 8; nt++) {
                const int c0 = nt * 8 + 2 * t;
                sacc[nt][0] = ((wA >> c0) & 1ull) ? -1e9f : sacc[nt][0] * scale;
                sacc[nt][1] = ((wA >> (c0 + 1)) & 1ull) ? -1e9f : sacc[nt][1] * scale;
                sacc[nt][2] = ((wB >> c0) & 1ull) ? -1e9f : sacc[nt][2] * scale;
                sacc[nt][3] = ((wB >> (c0 + 1)) & 1ull) ? -1e9f : sacc[nt][3] * scale;
            }
        }

        // ---- Online softmax
        float mxA = -INFINITY, mxB = -INFINITY;
#pragma unroll
        for (int nt = 0; nt < 8; nt++) {
            mxA = fmaxf(mxA, fmaxf(sacc[nt][0], sacc[nt][1]));
            mxB = fmaxf(mxB, fmaxf(sacc[nt][2], sacc[nt][3]));
        }
        mxA = fmaxf(mxA, __shfl_xor_sync(0xffffffffu, mxA, 1));
        mxA = fmaxf(mxA, __shfl_xor_sync(0xffffffffu, mxA, 2));
        mxB = fmaxf(mxB, __shfl_xor_sync(0xffffffffu, mxB, 1));
        mxB = fmaxf(mxB, __shfl_xor_sync(0xffffffffu, mxB, 2));

        const float mnA = fmaxf(mA, mxA);
        const float mnB = fmaxf(mB, mxB);
        const float cA = __expf(mA - mnA);
        const float cB = __expf(mB - mnB);
        float suA = 0.f, suB = 0.f;
#pragma unroll
        for (int nt = 0; nt < 8; nt++) {
            sacc[nt][0] = __expf(sacc[nt][0] - mnA);
            sacc[nt][1] = __expf(sacc[nt][1] - mnA);
            sacc[nt][2] = __expf(sacc[nt][2] - mnB);
            sacc[nt][3] = __expf(sacc[nt][3] - mnB);
            suA += sacc[nt][0] + sacc[nt][1];
            suB += sacc[nt][2] + sacc[nt][3];
        }
        suA += __shfl_xor_sync(0xffffffffu, suA, 1);
        suA += __shfl_xor_sync(0xffffffffu, suA, 2);
        suB += __shfl_xor_sync(0xffffffffu, suB, 1);
        suB += __shfl_xor_sync(0xffffffffu, suB, 2);
        lA = lA * cA + suA;
        lB = lB * cB + suB;
        mA = mnA;
        mB = mnB;
#pragma unroll
        for (int nt = 0; nt < 8; nt++) {
            oacc[nt][0] *= cA; oacc[nt][1] *= cA;
            oacc[nt][2] *= cB; oacc[nt][3] *= cB;
        }

        // ---- P A-fragments direct from registers (R12-validated mapping)
        uint32_t pf[4][4];
#pragma unroll
        for (int s = 0; s < 4; s++) {
            pf[s][0] = pack_bf16x2(sacc[2 * s][0],     sacc[2 * s][1]);
            pf[s][1] = pack_bf16x2(sacc[2 * s][2],     sacc[2 * s][3]);
            pf[s][2] = pack_bf16x2(sacc[2 * s + 1][0], sacc[2 * s + 1][1]);
            pf[s][3] = pack_bf16x2(sacc[2 * s + 1][2], sacc[2 * s + 1][3]);
        }

        // ---- O += P V
#pragma unroll
        for (int s = 0; s < 4; s++) {
            const uint32_t ks = (uint32_t)s * 32u;
#pragma unroll
            for (int ntp = 0; ntp < 4; ntp++) {
                uint32_t bq[4];
                ldsm_x4(bq, svw[b] + boffA[ntp] + ks);
                mma_bf16(oacc[2 * ntp],     pf[s], bq);
                mma_bf16(oacc[2 * ntp + 1], pf[s], bq + 2);
            }
        }
        b = (b == 2) ? 0 : b + 1;
        bn = (bn == 2) ? 0 : bn + 1;
    }

    // ---- Normalize + write O as bf16
    const float iA = 1.f / lA;
    const float iB = 1.f / lB;
    __nv_bfloat16* Og = O + ((size_t)grp * SLEN + qb * 128 + r0) * HEADDIM;
#pragma unroll
    for (int nt = 0; nt < 8; nt++) {
        const int cb = nt * 8 + 2 * t;
        uint32_t wA = pack_bf16x2(oacc[nt][0] * iA, oacc[nt][1] * iA);
        uint32_t wB = pack_bf16x2(oacc[nt][2] * iB, oacc[nt][3] * iB);
        *reinterpret_cast<uint32_t*>(Og + (size_t)gq * HEADDIM + cb) = wA;
        *reinterpret_cast<uint32_t*>(Og + (size_t)(gq + 8) * HEADDIM + cb) = wB;
    }
}

// ---------------------------------------------------------------------------
// Fused residual + LayerNorm (unchanged)
// ---------------------------------------------------------------------------
__global__ __launch_bounds__(256) void ln_kernel(
    const float* __restrict__ x, const float* __restrict__ p,
    const float* __restrict__ gamma, const float* __restrict__ beta,
    float* __restrict__ out)
{
    const int row = blockIdx.x;
    const int t = threadIdx.x;
    const size_t base = (size_t)row * DMODEL + t * 4;

    float4 xv = *(const float4*)(x + base);
    float4 pv = *(const float4*)(p + base);
    float v0 = xv.x + pv.x, v1 = xv.y + pv.y, v2 = xv.z + pv.z, v3 = xv.w + pv.w;

    __shared__ float red[8];
    float s = v0 + v1 + v2 + v3;
#pragma unroll
    for (int off = 16; off >= 1; off >>= 1) s += __shfl_xor_sync(0xffffffffu, s, off);
    if ((t & 31) == 0) red[t >> 5] = s;
    __syncthreads();
    float mu = (red[0] + red[1] + red[2] + red[3] +
                red[4] + red[5] + red[6] + red[7]) * (1.f / DMODEL);
    __syncthreads();

    float d0 = v0 - mu, d1 = v1 - mu, d2 = v2 - mu, d3 = v3 - mu;
    float q = d0 * d0 + d1 * d1 + d2 * d2 + d3 * d3;
#pragma unroll
    for (int off = 16; off >= 1; off >>= 1) q += __shfl_xor_sync(0xffffffffu, q, off);
    if ((t & 31) == 0) red[t >> 5] = q;
    __syncthreads();
    float var = (red[0] + red[1] + red[2] + red[3] +
                 red[4] + red[5] + red[6] + red[7]) * (1.f / DMODEL);
    float rs = rsqrtf(var + 1e-5f);

    float4 gv = *(const float4*)(gamma + t * 4);
    float4 bv = *(const float4*)(beta + t * 4);
    float4 ov;
    ov.x = d0 * rs * gv.x + bv.x;
    ov.y = d1 * rs * gv.y + bv.y;
    ov.z = d2 * rs * gv.z + bv.z;
    ov.w = d3 * rs * gv.w + bv.w;
    *(float4*)(out + base) = ov;
}

// ---------------------------------------------------------------------------
// Launch
// ---------------------------------------------------------------------------
extern "C" void kernel_launch(void* const* d_in, const int* in_sizes, int n_in,
                              void* d_out, int out_size)
{
    (void)in_sizes; (void)n_in; (void)out_size;
    const float* q_in  = (const float*)d_in[0];
    const float* k_in  = (const float*)d_in[1];
    const float* v_in  = (const float*)d_in[2];
    const unsigned char* mask = (const unsigned char*)d_in[3];
    const float* Wq = (const float*)d_in[4];
    const float* Wk = (const float*)d_in[5];
    const float* Wv = (const float*)d_in[6];
    const float* Wo = (const float*)d_in[7];
    const float* bo = (const float*)d_in[8];
    const float* gamma = (const float*)d_in[9];
    const float* beta  = (const float*)d_in[10];
    float* out = (float*)d_out;

    float* pP;
    __nv_bfloat16 *pQb, *pKb, *pVb, *pVTb, *pOb, *pQin, *pKin, *pVin;
    __nv_bfloat16 *pWqT, *pWkT, *pWvT, *pWoT;
    unsigned long long* pMb;
    cudaGetSymbolAddress((void**)&pP, g_P);
    cudaGetSymbolAddress((void**)&pQb, g_Qb);
    cudaGetSymbolAddress((void**)&pKb, g_Kb);
    cudaGetSymbolAddress((void**)&pVb, g_Vb);
    cudaGetSymbolAddress((void**)&pVTb, g_VTb);
    cudaGetSymbolAddress((void**)&pOb, g_Ob);
    cudaGetSymbolAddress((void**)&pQin, g_Qin);
    cudaGetSymbolAddress((void**)&pKin, g_Kin);
    cudaGetSymbolAddress((void**)&pVin, g_Vin);
    cudaGetSymbolAddress((void**)&pWqT, g_WqT);
    cudaGetSymbolAddress((void**)&pWkT, g_WkT);
    cudaGetSymbolAddress((void**)&pWvT, g_WvT);
    cudaGetSymbolAddress((void**)&pWoT, g_WoT);
    cudaGetSymbolAddress((void**)&pMb, g_Mb);

    cudaFuncSetAttribute(gemm_bf16_qkv, cudaFuncAttributeMaxDynamicSharedMemorySize, GEMM_SMEM);
    cudaFuncSetAttribute(gemm_bf16_out, cudaFuncAttributeMaxDynamicSharedMemorySize, GEMM_SMEM);
    cudaFuncSetAttribute(attn_bf16, cudaFuncAttributeMaxDynamicSharedMemorySize, ATT_SMEM);

    // launch 0: fused prep (weight transposes + input cvt + mask pack)
    prep_fused<<<PREP_BLOCKS, 256>>>(
        Wq, Wk, Wv, Wo, pWqT, pWkT, pWvT, pWoT,
        q_in, k_in, v_in, pQin, pKin, pVin,
        mask, pMb);

    // launch 1: batched Q/K/V projections
    dim3 ggrid3(DMODEL / 128, NROWS / 128, 3);
    gemm_bf16_qkv<<<ggrid3, 256, GEMM_SMEM>>>(
        pQin, pKin, pVin, pWqT, pWkT, pWvT, pQb, pKb, pVb,
        NROWS, DMODEL, DMODEL);

    // launch 2: V -> VT per group
    dim3 vgrid(SLEN / 32, HEADDIM / 32, NGROUPS);
    dim3 tblk(32, 8);
    vtranspose_bf16<<<vgrid, tblk>>>(pVb, pVTb);

    // launch 3: attention
    dim3 agrid(SLEN / 128, NGROUPS);
    attn_bf16<<<agrid, 256, ATT_SMEM>>>(pQb, pKb, pVTb, pMb, pOb);

    // launch 4: output projection (+bias, fp32 out)
    dim3 ggrid1(DMODEL / 128, NROWS / 128);
    gemm_bf16_out<<<ggrid1, 256, GEMM_SMEM>>>(pOb, pWoT, bo, pP, NROWS, DMODEL, DMODEL);

    // launch 5: residual + LayerNorm
    ln_kernel<<<NROWS, 256>>>(q_in, pP, gamma, beta, out);
}

// round 17
// speedup vs baseline: 1.2420x; 1.0101x over previous
#include <cuda_runtime.h>
#include <cuda_bf16.h>
#include <math.h>
#include <cstdint>

// Problem constants
#define BATCH   2
#define SLEN    2048
#define DMODEL  1024
#define NHEADS  16
#define HEADDIM 64
#define NROWS   (BATCH * SLEN)      // 4096
#define NGROUPS (BATCH * NHEADS)    // 32 reshaped "heads"

// Scratch (allocation-free rule: __device__ globals)
__device__ float g_P[NROWS * DMODEL];
__device__ __nv_bfloat16 g_Qb[NROWS * DMODEL];
__device__ __nv_bfloat16 g_Kb[NROWS * DMODEL];
__device__ __nv_bfloat16 g_Vb[NROWS * DMODEL];
__device__ __nv_bfloat16 g_VTb[NROWS * DMODEL];  // per-group transposed V
__device__ __nv_bfloat16 g_Ob[NROWS * DMODEL];
__device__ __nv_bfloat16 g_Qin[NROWS * DMODEL];
__device__ __nv_bfloat16 g_Kin[NROWS * DMODEL];
__device__ __nv_bfloat16 g_Vin[NROWS * DMODEL];
__device__ __nv_bfloat16 g_WqT[DMODEL * DMODEL];
__device__ __nv_bfloat16 g_WkT[DMODEL * DMODEL];
__device__ __nv_bfloat16 g_WvT[DMODEL * DMODEL];
__device__ __nv_bfloat16 g_WoT[DMODEL * DMODEL];
__device__ unsigned long long g_Mb[BATCH * SLEN * (SLEN / 64)];  // packed mask bits

// ---------------------------------------------------------------------------
// Helpers (sm_80+ only — compute_103 rejects 'a'-gated PTX like tcgen05)
// ---------------------------------------------------------------------------
__device__ __forceinline__ uint32_t smem_u32(const void* p) {
    uint32_t a;
    asm("{ .reg .u64 t; cvta.to.shared.u64 t, %1; cvt.u32.u64 %0, t; }"
        : "=r"(a) : "l"(p));
    return a;
}

__device__ __forceinline__ void cp_async16(uint32_t saddr, const void* gaddr) {
    asm volatile("cp.async.cg.shared.global [%0], [%1], 16;"
                 :: "r"(saddr), "l"(gaddr) : "memory");
}
#define CP_COMMIT() asm volatile("cp.async.commit_group;" ::: "memory")
#define CP_WAIT1()  asm volatile("cp.async.wait_group 1;" ::: "memory")

__device__ __forceinline__ void mma_bf16(float* d, const uint32_t* a, const uint32_t* b) {
    asm volatile(
        "mma.sync.aligned.m16n8k16.row.col.f32.bf16.bf16.f32 "
        "{%0,%1,%2,%3}, {%4,%5,%6,%7}, {%8,%9}, {%0,%1,%2,%3};"
        : "+f"(d[0]), "+f"(d[1]), "+f"(d[2]), "+f"(d[3])
        : "r"(a[0]), "r"(a[1]), "r"(a[2]), "r"(a[3]), "r"(b[0]), "r"(b[1]));
}

__device__ __forceinline__ void ldsm_x4(uint32_t* r, uint32_t saddr) {
    asm volatile("ldmatrix.sync.aligned.m8n8.x4.shared.b16 {%0,%1,%2,%3}, [%4];"
                 : "=r"(r[0]), "=r"(r[1]), "=r"(r[2]), "=r"(r[3]) : "r"(saddr));
}

__device__ __forceinline__ uint32_t pack_bf16x2(float lo, float hi) {
    __nv_bfloat162 h = __floats2bfloat162_rn(lo, hi);
    return *reinterpret_cast<uint32_t*>(&h);
}

__device__ __forceinline__ float ex2_approx(float x) {
    float y;
    asm("ex2.approx.f32 %0, %1;" : "=f"(y) : "f"(x));
    return y;
}

#define L2E 1.4426950408889634f

// ---------------------------------------------------------------------------
// Fused prep kernel (R16-validated): weight transposes + input cvt + mask pack
// ---------------------------------------------------------------------------
#define PREP_WT_BLOCKS   4096
#define PREP_CVT_BLOCKS  6144
#define PREP_MB_BLOCKS   512
#define PREP_BLOCKS (PREP_WT_BLOCKS + PREP_CVT_BLOCKS + PREP_MB_BLOCKS)

__global__ __launch_bounds__(256) void prep_fused(
    const float* __restrict__ W0, const float* __restrict__ W1,
    const float* __restrict__ W2, const float* __restrict__ W3,
    __nv_bfloat16* __restrict__ T0, __nv_bfloat16* __restrict__ T1,
    __nv_bfloat16* __restrict__ T2, __nv_bfloat16* __restrict__ T3,
    const float* __restrict__ x0, const float* __restrict__ x1,
    const float* __restrict__ x2,
    __nv_bfloat16* __restrict__ y0, __nv_bfloat16* __restrict__ y1,
    __nv_bfloat16* __restrict__ y2,
    const unsigned char* __restrict__ m, unsigned long long* __restrict__ mb)
{
    const int bid = blockIdx.x;
    const int tid = threadIdx.x;

    if (bid < PREP_WT_BLOCKS) {
        __shared__ float t[32][33];
        const int z = bid >> 10;
        const int rem = bid & 1023;
        const int bx = (rem & 31) * 32;
        const int by = (rem >> 5) * 32;
        const float* W = (z == 0) ? W0 : (z == 1) ? W1 : (z == 2) ? W2 : W3;
        __nv_bfloat16* Wt = (z == 0) ? T0 : (z == 1) ? T1 : (z == 2) ? T2 : T3;
        const int x = tid & 31;
        const int y = tid >> 5;
#pragma unroll
        for (int i = 0; i < 32; i += 8)
            t[y + i][x] = W[(size_t)(by + y + i) * DMODEL + bx + x];
        __syncthreads();
#pragma unroll
        for (int i = 0; i < 32; i += 8)
            Wt[(size_t)(bx + y + i) * DMODEL + by + x] = __float2bfloat16_rn(t[x][y + i]);
    } else if (bid < PREP_WT_BLOCKS + PREP_CVT_BLOCKS) {
        const int i0 = bid - PREP_WT_BLOCKS;
        const int z = i0 / 2048;
        const int blk = i0 % 2048;
        const float* x = (z == 0) ? x0 : (z == 1) ? x1 : x2;
        __nv_bfloat16* y = (z == 0) ? y0 : (z == 1) ? y1 : y2;
        const size_t i = ((size_t)blk * 256 + tid) * 8;
        float4 a = *(const float4*)(x + i);
        float4 b = *(const float4*)(x + i + 4);
        __nv_bfloat162* yp = reinterpret_cast<__nv_bfloat162*>(y + i);
        yp[0] = __floats2bfloat162_rn(a.x, a.y);
        yp[1] = __floats2bfloat162_rn(a.z, a.w);
        yp[2] = __floats2bfloat162_rn(b.x, b.y);
        yp[3] = __floats2bfloat162_rn(b.z, b.w);
    } else {
        const int blk = bid - PREP_WT_BLOCKS - PREP_CVT_BLOCKS;
        const int idx = blk * 256 + tid;
        const uint4* p4 = reinterpret_cast<const uint4*>(m + (size_t)idx * 64);
        unsigned long long w = 0;
#pragma unroll
        for (int q = 0; q < 4; q++) {
            uint4 v = p4[q];
            uint32_t b = ((v.x * 0x01020408u) >> 24) & 0xFu;
            b |= (((v.y * 0x01020408u) >> 24) & 0xFu) << 4;
            b |= (((v.z * 0x01020408u) >> 24) & 0xFu) << 8;
            b |= (((v.w * 0x01020408u) >> 24) & 0xFu) << 12;
            w |= (unsigned long long)b << (q * 16);
        }
        mb[idx] = w;
    }
}

// ---------------------------------------------------------------------------
// V transpose per group (bf16): V[g][s][d] -> VT[g][d][s]
// ---------------------------------------------------------------------------
__global__ __launch_bounds__(256) void vtranspose_bf16(
    const __nv_bfloat16* __restrict__ V, __nv_bfloat16* __restrict__ VT)
{
    __shared__ __nv_bfloat16 t[32][34];
    const int g = blockIdx.z;
    const int s0 = blockIdx.x * 32, d0 = blockIdx.y * 32;
    const int x = threadIdx.x, y = threadIdx.y;
    const __nv_bfloat16* Vg = V + (size_t)g * SLEN * HEADDIM;
    __nv_bfloat16* VTg = VT + (size_t)g * SLEN * HEADDIM;
#pragma unroll
    for (int i = 0; i < 32; i += 8)
        t[y + i][x] = Vg[(size_t)(s0 + y + i) * HEADDIM + d0 + x];
    __syncthreads();
#pragma unroll
    for (int i = 0; i < 32; i += 8)
        VTg[(size_t)(d0 + y + i) * SLEN + s0 + x] = t[x][y + i];
}

// ---------------------------------------------------------------------------
// HMMA bf16 GEMM (R15-validated): 3-stage cp.async, launch_bounds(256,2).
// ---------------------------------------------------------------------------
#define KSW 36
#define TILE_WORDS (128 * KSW)
#define GEMM_SMEM (6 * TILE_WORDS * 4)   // 110592 B

__global__ __launch_bounds__(256, 2) void gemm_bf16_qkv(
    const __nv_bfloat16* __restrict__ A0, const __nv_bfloat16* __restrict__ A1,
    const __nv_bfloat16* __restrict__ A2,
    const __nv_bfloat16* __restrict__ B0, const __nv_bfloat16* __restrict__ B1,
    const __nv_bfloat16* __restrict__ B2,
    __nv_bfloat16* __restrict__ C0, __nv_bfloat16* __restrict__ C1,
    __nv_bfloat16* __restrict__ C2, int M, int N, int K)
{
    extern __shared__ uint32_t shw[];

    const int z = blockIdx.z;
    const __nv_bfloat16* A = (z == 0) ? A0 : (z == 1) ? A1 : A2;
    const __nv_bfloat16* Bt = (z == 0) ? B0 : (z == 1) ? B1 : B2;
    __nv_bfloat16* C = (z == 0) ? C0 : (z == 1) ? C1 : C2;

    const int tid = threadIdx.x;
    const int wid = tid >> 5;
    const int lane = tid & 31;
    const int mb = (wid & 3) * 32;
    const int nb = (wid >> 2) * 64;
    const int g = lane >> 2;
    const int t = lane & 3;
    const int m0 = blockIdx.y * 128;
    const int n0 = blockIdx.x * 128;

    const int quad = lane >> 3;
    const int within = lane & 7;
    const int arow = (quad & 1) * 8 + within;
    const int acol = (quad >> 1) * 4;
    const int brow = (quad >> 1) * 8 + within;
    const int bcol = (quad & 1) * 4;

    const uint32_t aoff0 = (uint32_t)((mb + arow) * KSW + acol) * 4u;
    const uint32_t aoff1 = (uint32_t)((mb + 16 + arow) * KSW + acol) * 4u;
    uint32_t boff[4];
#pragma unroll
    for (int ntp = 0; ntp < 4; ntp++)
        boff[ntp] = (uint32_t)((nb + ntp * 16 + brow) * KSW + bcol) * 4u;

    uint32_t saw[3], sbw[3];
#pragma unroll
    for (int s = 0; s < 3; s++) {
        saw[s] = smem_u32(shw + s * TILE_WORDS);
        sbw[s] = smem_u32(shw + (3 + s) * TILE_WORDS);
    }

    float acc[2][8][4];
#pragma unroll
    for (int i = 0; i < 2; i++)
#pragma unroll
        for (int j = 0; j < 8; j++)
#pragma unroll
            for (int q = 0; q < 4; q++) acc[i][j][q] = 0.f;

    const int NCH = K / 64;

    auto issue = [&](int c, int b) {
        const __nv_bfloat16* Ag = A + (size_t)m0 * K + (size_t)c * 64;
        const __nv_bfloat16* Bg = Bt + (size_t)n0 * K + (size_t)c * 64;
#pragma unroll
        for (int i = 0; i < 4; i++) {
            const int u = tid + 256 * i;
            const int row = u >> 3;
            const int seg = u & 7;
            const uint32_t so = (uint32_t)(row * KSW + seg * 4) * 4u;
            cp_async16(saw[b] + so, Ag + (size_t)row * K + seg * 8);
            cp_async16(sbw[b] + so, Bg + (size_t)row * K + seg * 8);
        }
        CP_COMMIT();
    };

    issue(0, 0);
    issue(1, 1);

    int b = 0, bn = 2;
    for (int c = 0; c < NCH; c++) {
        CP_WAIT1();
        __syncthreads();
        if (c + 2 < NCH) issue(c + 2, bn);
        else CP_COMMIT();
#pragma unroll
        for (int s = 0; s < 4; s++) {
            const uint32_t ks = (uint32_t)s * 32u;
            uint32_t af0[4], af1[4];
            ldsm_x4(af0, saw[b] + aoff0 + ks);
            ldsm_x4(af1, saw[b] + aoff1 + ks);
#pragma unroll
            for (int ntp = 0; ntp < 4; ntp++) {
                uint32_t bq[4];
                ldsm_x4(bq, sbw[b] + boff[ntp] + ks);
                mma_bf16(acc[0][2 * ntp],     af0, bq);
                mma_bf16(acc[1][2 * ntp],     af1, bq);
                mma_bf16(acc[0][2 * ntp + 1], af0, bq + 2);
                mma_bf16(acc[1][2 * ntp + 1], af1, bq + 2);
            }
        }
        b = (b == 2) ? 0 : b + 1;
        bn = (bn == 2) ? 0 : bn + 1;
    }

#pragma unroll
    for (int mt = 0; mt < 2; mt++) {
        const int r = m0 + mb + mt * 16 + g;
#pragma unroll
        for (int nt = 0; nt < 8; nt++) {
            const int cx = n0 + nb + nt * 8 + 2 * t;
            uint32_t w0 = pack_bf16x2(acc[mt][nt][0], acc[mt][nt][1]);
            uint32_t w1 = pack_bf16x2(acc[mt][nt][2], acc[mt][nt][3]);
            *reinterpret_cast<uint32_t*>(C + (size_t)r * N + cx) = w0;
            *reinterpret_cast<uint32_t*>(C + (size_t)(r + 8) * N + cx) = w1;
        }
    }
}

__global__ __launch_bounds__(256, 2) void gemm_bf16_out(
    const __nv_bfloat16* __restrict__ A, const __nv_bfloat16* __restrict__ Bt,
    const float* __restrict__ bias, float* __restrict__ C,
    int M, int N, int K)
{
    extern __shared__ uint32_t shw[];

    const int tid = threadIdx.x;
    const int wid = tid >> 5;
    const int lane = tid & 31;
    const int mb = (wid & 3) * 32;
    const int nb = (wid >> 2) * 64;
    const int g = lane >> 2;
    const int t = lane & 3;
    const int m0 = blockIdx.y * 128;
    const int n0 = blockIdx.x * 128;

    const int quad = lane >> 3;
    const int within = lane & 7;
    const int arow = (quad & 1) * 8 + within;
    const int acol = (quad >> 1) * 4;
    const int brow = (quad >> 1) * 8 + within;
    const int bcol = (quad & 1) * 4;

    const uint32_t aoff0 = (uint32_t)((mb + arow) * KSW + acol) * 4u;
    const uint32_t aoff1 = (uint32_t)((mb + 16 + arow) * KSW + acol) * 4u;
    uint32_t boff[4];
#pragma unroll
    for (int ntp = 0; ntp < 4; ntp++)
        boff[ntp] = (uint32_t)((nb + ntp * 16 + brow) * KSW + bcol) * 4u;

    uint32_t saw[3], sbw[3];
#pragma unroll
    for (int s = 0; s < 3; s++) {
        saw[s] = smem_u32(shw + s * TILE_WORDS);
        sbw[s] = smem_u32(shw + (3 + s) * TILE_WORDS);
    }

    float acc[2][8][4];
#pragma unroll
    for (int i = 0; i < 2; i++)
#pragma unroll
        for (int j = 0; j < 8; j++)
#pragma unroll
            for (int q = 0; q < 4; q++) acc[i][j][q] = 0.f;

    const int NCH = K / 64;

    auto issue = [&](int c, int b) {
        const __nv_bfloat16* Ag = A + (size_t)m0 * K + (size_t)c * 64;
        const __nv_bfloat16* Bg = Bt + (size_t)n0 * K + (size_t)c * 64;
#pragma unroll
        for (int i = 0; i < 4; i++) {
            const int u = tid + 256 * i;
            const int row = u >> 3;
            const int seg = u & 7;
            const uint32_t so = (uint32_t)(row * KSW + seg * 4) * 4u;
            cp_async16(saw[b] + so, Ag + (size_t)row * K + seg * 8);
            cp_async16(sbw[b] + so, Bg + (size_t)row * K + seg * 8);
        }
        CP_COMMIT();
    };

    issue(0, 0);
    issue(1, 1);

    int b = 0, bn = 2;
    for (int c = 0; c < NCH; c++) {
        CP_WAIT1();
        __syncthreads();
        if (c + 2 < NCH) issue(c + 2, bn);
        else CP_COMMIT();
#pragma unroll
        for (int s = 0; s < 4; s++) {
            const uint32_t ks = (uint32_t)s * 32u;
            uint32_t af0[4], af1[4];
            ldsm_x4(af0, saw[b] + aoff0 + ks);
            ldsm_x4(af1, saw[b] + aoff1 + ks);
#pragma unroll
            for (int ntp = 0; ntp < 4; ntp++) {
                uint32_t bq[4];
                ldsm_x4(bq, sbw[b] + boff[ntp] + ks);
                mma_bf16(acc[0][2 * ntp],     af0, bq);
                mma_bf16(acc[1][2 * ntp],     af1, bq);
                mma_bf16(acc[0][2 * ntp + 1], af0, bq + 2);
                mma_bf16(acc[1][2 * ntp + 1], af1, bq + 2);
            }
        }
        b = (b == 2) ? 0 : b + 1;
        bn = (bn == 2) ? 0 : bn + 1;
    }

#pragma unroll
    for (int mt = 0; mt < 2; mt++) {
        const int r = m0 + mb + mt * 16 + g;
#pragma unroll
        for (int nt = 0; nt < 8; nt++) {
            const int cx = n0 + nb + nt * 8 + 2 * t;
            const float b0 = __ldg(&bias[cx]);
            const float b1 = __ldg(&bias[cx + 1]);
            float2 v0, v1;
            v0.x = acc[mt][nt][0] + b0; v0.y = acc[mt][nt][1] + b1;
            v1.x = acc[mt][nt][2] + b0; v1.y = acc[mt][nt][3] + b1;
            *(float2*)(C + (size_t)r * N + cx) = v0;
            *(float2*)(C + (size_t)(r + 8) * N + cx) = v1;
        }
    }
}

// ---------------------------------------------------------------------------
// bf16 HMMA flash attention. P in registers (R12), packed-bit mask (R13),
// 3-stage pipeline + launch_bounds(256,2) (R15).
// R17: fast-path softmax folds scale+shift+log2e into ONE FFMA per score:
//   p = ex2(s * (scale*log2e) + (-m*log2e))   [2 slots/score vs 4]
// Max-reduce runs on raw scores, converted once: mn = max(m, mx*scale).
// Slow path (any masked bit in tile) keeps exact R15 semantics.
// ---------------------------------------------------------------------------
#define AKW 36
#define ATT_TILE (64 * AKW)
#define ATT_SMEM (6 * ATT_TILE * 4)   // 55296 B

__global__ __launch_bounds__(256, 2) void attn_bf16(
    const __nv_bfloat16* __restrict__ Q, const __nv_bfloat16* __restrict__ K,
    const __nv_bfloat16* __restrict__ VT,
    const unsigned long long* __restrict__ maskbits,
    __nv_bfloat16* __restrict__ O)
{
    extern __shared__ uint32_t smw[];

    const int tid = threadIdx.x;
    const int wid = tid >> 5;
    const int lane = tid & 31;
    const int gq = lane >> 2;
    const int t = lane & 3;
    const int qb = blockIdx.x;
    const int grp = blockIdx.y;
    const int r0 = wid * 16;

    const int quad = lane >> 3;
    const int within = lane & 7;
    const int arow = (quad & 1) * 8 + within;
    const int acol = (quad >> 1) * 4;
    const int brow = (quad >> 1) * 8 + within;
    const int bcol = (quad & 1) * 4;

    uint32_t boffA[4];
#pragma unroll
    for (int ntp = 0; ntp < 4; ntp++)
        boffA[ntp] = (uint32_t)((ntp * 16 + brow) * AKW + bcol) * 4u;

    uint32_t skw[3], svw[3];
#pragma unroll
    for (int s = 0; s < 3; s++) {
        skw[s] = smem_u32(smw + s * ATT_TILE);
        svw[s] = smem_u32(smw + (3 + s) * ATT_TILE);
    }

    const __nv_bfloat16* Qg = Q + ((size_t)grp * SLEN + qb * 128 + r0) * HEADDIM;
    const __nv_bfloat16* Kg = K + (size_t)grp * SLEN * HEADDIM;
    const __nv_bfloat16* VTg = VT + (size_t)grp * SLEN * HEADDIM;
    const unsigned long long* mw =
        maskbits + ((size_t)(grp % BATCH) * SLEN + (size_t)(qb * 128 + r0)) * (SLEN / 64);

    auto issue = [&](int kt, int b) {
#pragma unroll
        for (int i = 0; i < 2; i++) {
            const int u = tid + 256 * i;
            const int row = u >> 3;
            const int seg = u & 7;
            const uint32_t so = (uint32_t)(row * AKW + seg * 4) * 4u;
            cp_async16(skw[b] + so, Kg + (size_t)(kt * 64 + row) * HEADDIM + seg * 8);
            cp_async16(svw[b] + so, VTg + (size_t)row * SLEN + kt * 64 + seg * 8);
        }
        CP_COMMIT();
    };

    // ---- Stage Q through tile buffers, build persistent A fragments
    uint32_t* sQw = smw + r0 * AKW;
    const uint32_t sq_addr = smem_u32(sQw) + (uint32_t)(arow * AKW + acol) * 4u;
    {
        const int row = lane >> 1;
        const int cs = (lane & 1) * 16;
#pragma unroll
        for (int j = 0; j < 4; j++) {
            uint4 v = *(const uint4*)(Qg + (size_t)row * HEADDIM + (cs + j * 4) * 2);
            *(uint4*)&sQw[row * AKW + cs + j * 4] = v;
        }
    }
    __syncwarp();
    uint32_t qf[4][4];
#pragma unroll
    for (int s = 0; s < 4; s++)
        ldsm_x4(qf[s], sq_addr + (uint32_t)s * 32u);
    __syncthreads();

    issue(0, 0);
    issue(1, 1);

    float oacc[8][4];
#pragma unroll
    for (int nt = 0; nt < 8; nt++)
#pragma unroll
        for (int q = 0; q < 4; q++) oacc[nt][q] = 0.f;
    float mA = -INFINITY, mB = -INFINITY, lA = 0.f, lB = 0.f;

    const float scale = 0.125f;            // 1/sqrt(64)
    const float c1 = 0.125f * L2E;         // scale * log2(e)
    const int NT = SLEN / 64;

    int b = 0, bn = 2;
    for (int kt = 0; kt < NT; kt++) {
        CP_WAIT1();
        __syncthreads();
        if (kt + 2 < NT) issue(kt + 2, bn);
        else CP_COMMIT();

        // ---- S = Q K^T  (raw, unscaled)
        float sacc[8][4];
#pragma unroll
        for (int nt = 0; nt < 8; nt++)
#pragma unroll
            for (int q = 0; q < 4; q++) sacc[nt][q] = 0.f;
#pragma unroll
        for (int s = 0; s < 4; s++) {
            const uint32_t ks = (uint32_t)s * 32u;
#pragma unroll
            for (int ntp = 0; ntp < 4; ntp++) {
                uint32_t bq[4];
                ldsm_x4(bq, skw[b] + boffA[ntp] + ks);
                mma_bf16(sacc[2 * ntp],     qf[s], bq);
                mma_bf16(sacc[2 * ntp + 1], qf[s], bq + 2);
            }
        }

        const unsigned long long wA = mw[(size_t)gq * (SLEN / 64) + kt];
        const unsigned long long wB = mw[(size_t)(gq + 8) * (SLEN / 64) + kt];
        if (__all_sync(0xffffffffu, (wA | wB) == 0ull)) {
            // ===== FAST PATH: folded exp, max on raw scores =====
            float mxA = -INFINITY, mxB = -INFINITY;
#pragma unroll
            for (int nt = 0; nt < 8; nt++) {
                mxA = fmaxf(mxA, fmaxf(sacc[nt][0], sacc[nt][1]));
                mxB = fmaxf(mxB, fmaxf(sacc[nt][2], sacc[nt][3]));
            }
            mxA = fmaxf(mxA, __shfl_xor_sync(0xffffffffu, mxA, 1));
            mxA = fmaxf(mxA, __shfl_xor_sync(0xffffffffu, mxA, 2));
            mxB = fmaxf(mxB, __shfl_xor_sync(0xffffffffu, mxB, 1));
            mxB = fmaxf(mxB, __shfl_xor_sync(0xffffffffu, mxB, 2));

            const float mnA = fmaxf(mA, mxA * scale);
            const float mnB = fmaxf(mB, mxB * scale);
            const float cA = ex2_approx((mA - mnA) * L2E);   // exp(mA-mnA); 0 when mA=-inf
            const float cB = ex2_approx((mB - mnB) * L2E);
            const float dA = -mnA * L2E;
            const float dB = -mnB * L2E;

            float suA = 0.f, suB = 0.f;
#pragma unroll
            for (int nt = 0; nt < 8; nt++) {
                sacc[nt][0] = ex2_approx(fmaf(sacc[nt][0], c1, dA));
                sacc[nt][1] = ex2_approx(fmaf(sacc[nt][1], c1, dA));
                sacc[nt][2] = ex2_approx(fmaf(sacc[nt][2], c1, dB));
                sacc[nt][3] = ex2_approx(fmaf(sacc[nt][3], c1, dB));
                suA += sacc[nt][0] + sacc[nt][1];
                suB += sacc[nt][2] + sacc[nt][3];
            }
            suA += __shfl_xor_sync(0xffffffffu, suA, 1);
            suA += __shfl_xor_sync(0xffffffffu, suA, 2);
            suB += __shfl_xor_sync(0xffffffffu, suB, 1);
            suB += __shfl_xor_sync(0xffffffffu, suB, 2);
            lA = lA * cA + suA;
            lB = lB * cB + suB;
            mA = mnA;
            mB = mnB;
#pragma unroll
            for (int nt = 0; nt < 8; nt++) {
                oacc[nt][0] *= cA; oacc[nt][1] *= cA;
                oacc[nt][2] *= cB; oacc[nt][3] *= cB;
            }
        } else {
            // ===== SLOW PATH: exact R15 semantics (scaled scores, -1e9 mask) =====
#pragma unroll
            for (int nt = 0; nt < 8; nt++) {
                const int c0 = nt * 8 + 2 * t;
                sacc[nt][0] = ((wA >> c0) & 1ull) ? -1e9f : sacc[nt][0] * scale;
                sacc[nt][1] = ((wA >> (c0 + 1)) & 1ull) ? -1e9f : sacc[nt][1] * scale;
                sacc[nt][2] = ((wB >> c0) & 1ull) ? -1e9f : sacc[nt][2] * scale;
                sacc[nt][3] = ((wB >> (c0 + 1)) & 1ull) ? -1e9f : sacc[nt][3] * scale;
            }
            float mxA = -INFINITY, mxB = -INFINITY;
#pragma unroll
            for (int nt = 0; nt < 8; nt++) {
                mxA = fmaxf(mxA, fmaxf(sacc[nt][0], sacc[nt][1]));
                mxB = fmaxf(mxB, fmaxf(sacc[nt][2], sacc[nt][3]));
            }
            mxA = fmaxf(mxA, __shfl_xor_sync(0xffffffffu, mxA, 1));
            mxA = fmaxf(mxA, __shfl_xor_sync(0xffffffffu, mxA, 2));
            mxB = fmaxf(mxB, __shfl_xor_sync(0xffffffffu, mxB, 1));
            mxB = fmaxf(mxB, __shfl_xor_sync(0xffffffffu, mxB, 2));

            const float mnA = fmaxf(mA, mxA);
            const float mnB = fmaxf(mB, mxB);
            const float cA = __expf(mA - mnA);
            const float cB = __expf(mB - mnB);
            float suA = 0.f, suB = 0.f;
#pragma unroll
            for (int nt = 0; nt < 8; nt++) {
                sacc[nt][0] = __expf(sacc[nt][0] - mnA);
                sacc[nt][1] = __expf(sacc[nt][1] - mnA);
                sacc[nt][2] = __expf(sacc[nt][2] - mnB);
                sacc[nt][3] = __expf(sacc[nt][3] - mnB);
                suA += sacc[nt][0] + sacc[nt][1];
                suB += sacc[nt][2] + sacc[nt][3];
            }
            suA += __shfl_xor_sync(0xffffffffu, suA, 1);
            suA += __shfl_xor_sync(0xffffffffu, suA, 2);
            suB += __shfl_xor_sync(0xffffffffu, suB, 1);
            suB += __shfl_xor_sync(0xffffffffu, suB, 2);
            lA = lA * cA + suA;
            lB = lB * cB + suB;
            mA = mnA;
            mB = mnB;
#pragma unroll
            for (int nt = 0; nt < 8; nt++) {
                oacc[nt][0] *= cA; oacc[nt][1] *= cA;
                oacc[nt][2] *= cB; oacc[nt][3] *= cB;
            }
        }

        // ---- P A-fragments direct from registers (R12-validated mapping)
        uint32_t pf[4][4];
#pragma unroll
        for (int s = 0; s < 4; s++) {
            pf[s][0] = pack_bf16x2(sacc[2 * s][0],     sacc[2 * s][1]);
            pf[s][1] = pack_bf16x2(sacc[2 * s][2],     sacc[2 * s][3]);
            pf[s][2] = pack_bf16x2(sacc[2 * s + 1][0], sacc[2 * s + 1][1]);
            pf[s][3] = pack_bf16x2(sacc[2 * s + 1][2], sacc[2 * s + 1][3]);
        }

        // ---- O += P V
#pragma unroll
        for (int s = 0; s < 4; s++) {
            const uint32_t ks = (uint32_t)s * 32u;
#pragma unroll
            for (int ntp = 0; ntp < 4; ntp++) {
                uint32_t bq[4];
                ldsm_x4(bq, svw[b] + boffA[ntp] + ks);
                mma_bf16(oacc[2 * ntp],     pf[s], bq);
                mma_bf16(oacc[2 * ntp + 1], pf[s], bq + 2);
            }
        }
        b = (b == 2) ? 0 : b + 1;
        bn = (bn == 2) ? 0 : bn + 1;
    }

    // ---- Normalize + write O as bf16
    const float iA = 1.f / lA;
    const float iB = 1.f / lB;
    __nv_bfloat16* Og = O + ((size_t)grp * SLEN + qb * 128 + r0) * HEADDIM;
#pragma unroll
    for (int nt = 0; nt < 8; nt++) {
        const int cb = nt * 8 + 2 * t;
        uint32_t wA = pack_bf16x2(oacc[nt][0] * iA, oacc[nt][1] * iA);
        uint32_t wB = pack_bf16x2(oacc[nt][2] * iB, oacc[nt][3] * iB);
        *reinterpret_cast<uint32_t*>(Og + (size_t)gq * HEADDIM + cb) = wA;
        *reinterpret_cast<uint32_t*>(Og + (size_t)(gq + 8) * HEADDIM + cb) = wB;
    }
}

// ---------------------------------------------------------------------------
// Fused residual + LayerNorm (unchanged)
// ---------------------------------------------------------------------------
__global__ __launch_bounds__(256) void ln_kernel(
    const float* __restrict__ x, const float* __restrict__ p,
    const float* __restrict__ gamma, const float* __restrict__ beta,
    float* __restrict__ out)
{
    const int row = blockIdx.x;
    const int t = threadIdx.x;
    const size_t base = (size_t)row * DMODEL + t * 4;

    float4 xv = *(const float4*)(x + base);
    float4 pv = *(const float4*)(p + base);
    float v0 = xv.x + pv.x, v1 = xv.y + pv.y, v2 = xv.z + pv.z, v3 = xv.w + pv.w;

    __shared__ float red[8];
    float s = v0 + v1 + v2 + v3;
#pragma unroll
    for (int off = 16; off >= 1; off >>= 1) s += __shfl_xor_sync(0xffffffffu, s, off);
    if ((t & 31) == 0) red[t >> 5] = s;
    __syncthreads();
    float mu = (red[0] + red[1] + red[2] + red[3] +
                red[4] + red[5] + red[6] + red[7]) * (1.f / DMODEL);
    __syncthreads();

    float d0 = v0 - mu, d1 = v1 - mu, d2 = v2 - mu, d3 = v3 - mu;
    float q = d0 * d0 + d1 * d1 + d2 * d2 + d3 * d3;
#pragma unroll
    for (int off = 16; off >= 1; off >>= 1) q += __shfl_xor_sync(0xffffffffu, q, off);
    if ((t & 31) == 0) red[t >> 5] = q;
    __syncthreads();
    float var = (red[0] + red[1] + red[2] + red[3] +
                 red[4] + red[5] + red[6] + red[7]) * (1.f / DMODEL);
    float rs = rsqrtf(var + 1e-5f);

    float4 gv = *(const float4*)(gamma + t * 4);
    float4 bv = *(const float4*)(beta + t * 4);
    float4 ov;
    ov.x = d0 * rs * gv.x + bv.x;
    ov.y = d1 * rs * gv.y + bv.y;
    ov.z = d2 * rs * gv.z + bv.z;
    ov.w = d3 * rs * gv.w + bv.w;
    *(float4*)(out + base) = ov;
}

// ---------------------------------------------------------------------------
// Launch
// ---------------------------------------------------------------------------
extern "C" void kernel_launch(void* const* d_in, const int* in_sizes, int n_in,
                              void* d_out, int out_size)
{
    (void)in_sizes; (void)n_in; (void)out_size;
    const float* q_in  = (const float*)d_in[0];
    const float* k_in  = (const float*)d_in[1];
    const float* v_in  = (const float*)d_in[2];
    const unsigned char* mask = (const unsigned char*)d_in[3];
    const float* Wq = (const float*)d_in[4];
    const float* Wk = (const float*)d_in[5];
    const float* Wv = (const float*)d_in[6];
    const float* Wo = (const float*)d_in[7];
    const float* bo = (const float*)d_in[8];
    const float* gamma = (const float*)d_in[9];
    const float* beta  = (const float*)d_in[10];
    float* out = (float*)d_out;

    float* pP;
    __nv_bfloat16 *pQb, *pKb, *pVb, *pVTb, *pOb, *pQin, *pKin, *pVin;
    __nv_bfloat16 *pWqT, *pWkT, *pWvT, *pWoT;
    unsigned long long* pMb;
    cudaGetSymbolAddress((void**)&pP, g_P);
    cudaGetSymbolAddress((void**)&pQb, g_Qb);
    cudaGetSymbolAddress((void**)&pKb, g_Kb);
    cudaGetSymbolAddress((void**)&pVb, g_Vb);
    cudaGetSymbolAddress((void**)&pVTb, g_VTb);
    cudaGetSymbolAddress((void**)&pOb, g_Ob);
    cudaGetSymbolAddress((void**)&pQin, g_Qin);
    cudaGetSymbolAddress((void**)&pKin, g_Kin);
    cudaGetSymbolAddress((void**)&pVin, g_Vin);
    cudaGetSymbolAddress((void**)&pWqT, g_WqT);
    cudaGetSymbolAddress((void**)&pWkT, g_WkT);
    cudaGetSymbolAddress((void**)&pWvT, g_WvT);
    cudaGetSymbolAddress((void**)&pWoT, g_WoT);
    cudaGetSymbolAddress((void**)&pMb, g_Mb);

    cudaFuncSetAttribute(gemm_bf16_qkv, cudaFuncAttributeMaxDynamicSharedMemorySize, GEMM_SMEM);
    cudaFuncSetAttribute(gemm_bf16_out, cudaFuncAttributeMaxDynamicSharedMemorySize, GEMM_SMEM);
    cudaFuncSetAttribute(attn_bf16, cudaFuncAttributeMaxDynamicSharedMemorySize, ATT_SMEM);

    // launch 0: fused prep (weight transposes + input cvt + mask pack)
    prep_fused<<<PREP_BLOCKS, 256>>>(
        Wq, Wk, Wv, Wo, pWqT, pWkT, pWvT, pWoT,
        q_in, k_in, v_in, pQin, pKin, pVin,
        mask, pMb);

    // launch 1: batched Q/K/V projections
    dim3 ggrid3(DMODEL / 128, NROWS / 128, 3);
    gemm_bf16_qkv<<<ggrid3, 256, GEMM_SMEM>>>(
        pQin, pKin, pVin, pWqT, pWkT, pWvT, pQb, pKb, pVb,
        NROWS, DMODEL, DMODEL);

    // launch 2: V -> VT per group
    dim3 vgrid(SLEN / 32, HEADDIM / 32, NGROUPS);
    dim3 tblk(32, 8);
    vtranspose_bf16<<<vgrid, tblk>>>(pVb, pVTb);

    // launch 3: attention
    dim3 agrid(SLEN / 128, NGROUPS);
    attn_bf16<<<agrid, 256, ATT_SMEM>>>(pQb, pKb, pVTb, pMb, pOb);

    // launch 4: output projection (+bias, fp32 out)
    dim3 ggrid1(DMODEL / 128, NROWS / 128);
    gemm_bf16_out<<<ggrid1, 256, GEMM_SMEM>>>(pOb, pWoT, bo, pP, NROWS, DMODEL, DMODEL);

    // launch 5: residual + LayerNorm
    ln_kernel<<<NROWS, 256>>>(q_in, pP, gamma, beta, out);
}